// round 1
// baseline (speedup 1.0000x reference)
#include <cuda_runtime.h>
#include <math.h>

#define ROWS   8192
#define SEQ    4096
#define DM     1024
#define DI     2048
#define NH     8
#define HD     256
#define NS     64
#define CHK    64
#define NC     64
#define PROJ   5128
#define OFF_Z  0
#define OFF_X  2048
#define OFF_B  4096
#define OFF_C  4608
#define OFF_DT 5120
#define EPSV   1.1920929e-7f

// ------------------------- scratch (device globals) -------------------------
__device__ float g_normed[ROWS * DM];              // 32 MB
__device__ float g_proj[(size_t)ROWS * PROJ];      // 168 MB
__device__ float g_x[ROWS * DI];                   // 64 MB (silu(conv(x)))
__device__ float g_dt[ROWS * NH];                  // per-head dt
__device__ float g_GM[1024 * 4096];                // per chunk-head masked Gram, 16 MB
__device__ float g_lcse[1024 * 64];                // exp(cumsum)
__device__ float g_wl[1024 * 64];                  // exp(lcs[63]-lcs[l])
__device__ float g_decay[1024];                    // exp(lcs[63])
__device__ float g_y[ROWS * DI];                   // ssd output (intra+inter)
__device__ float g_yn[ROWS * DI];                  // gated+normed

// ------------------------- helpers -------------------------
__device__ __forceinline__ float blk_reduce_sum(float v, float* red) {
    int tid = threadIdx.x;
    #pragma unroll
    for (int o = 16; o > 0; o >>= 1) v += __shfl_xor_sync(0xffffffffu, v, o);
    if ((tid & 31) == 0) red[tid >> 5] = v;
    __syncthreads();
    if (tid < 8) {
        float t = red[tid];
        #pragma unroll
        for (int o = 4; o > 0; o >>= 1) t += __shfl_xor_sync(0xffu, t, o);
        if (tid == 0) red[0] = t;
    }
    __syncthreads();
    return red[0];
}

// ------------------------- K1: input RMSNorm -------------------------
__global__ __launch_bounds__(256) void k_rms_in(const float* __restrict__ hidden,
                                                const float* __restrict__ w) {
    int row = blockIdx.x, tid = threadIdx.x;
    __shared__ float red[8];
    float4 v = ((const float4*)(hidden + (size_t)row * DM))[tid];
    float ss = v.x * v.x + v.y * v.y + v.z * v.z + v.w * v.w;
    ss = blk_reduce_sum(ss, red);
    float sc = rsqrtf(ss * (1.0f / DM) + EPSV);
    float4 wv = ((const float4*)w)[tid];
    float4 o;
    o.x = v.x * sc * wv.x; o.y = v.y * sc * wv.y;
    o.z = v.z * sc * wv.z; o.w = v.w * sc * wv.w;
    ((float4*)(g_normed + (size_t)row * DM))[tid] = o;
}

// ------------------------- SGEMM: C = A@B (+ R) -------------------------
// A: MxK row-major, B: KxN row-major. BM=BN=128, BK=8, 256 thr, 8x8/thread.
__global__ __launch_bounds__(256) void sgemm(const float* __restrict__ A,
                                             const float* __restrict__ B,
                                             const float* __restrict__ R,
                                             float* __restrict__ C,
                                             int M, int N, int K, int addR) {
    __shared__ float As[8][128];
    __shared__ float Bs[8][128];
    int tid = threadIdx.x;
    int bm = blockIdx.y * 128, bn = blockIdx.x * 128;
    int arow = tid >> 1, acol = (tid & 1) * 4;
    int brow = tid >> 5, bcol = (tid & 31) * 4;
    int ty = tid >> 4, tx = tid & 15;
    float acc[8][8];
    #pragma unroll
    for (int i = 0; i < 8; i++)
        #pragma unroll
        for (int j = 0; j < 8; j++) acc[i][j] = 0.f;

    for (int k0 = 0; k0 < K; k0 += 8) {
        float4 av = *(const float4*)(A + (size_t)(bm + arow) * K + k0 + acol);
        As[acol + 0][arow] = av.x; As[acol + 1][arow] = av.y;
        As[acol + 2][arow] = av.z; As[acol + 3][arow] = av.w;
        float4 bv = make_float4(0.f, 0.f, 0.f, 0.f);
        if (bn + bcol < N) bv = *(const float4*)(B + (size_t)(k0 + brow) * N + bn + bcol);
        *(float4*)&Bs[brow][bcol] = bv;
        __syncthreads();
        #pragma unroll
        for (int kk = 0; kk < 8; kk++) {
            float4 ra0 = *(float4*)&As[kk][ty * 8];
            float4 ra1 = *(float4*)&As[kk][ty * 8 + 4];
            float4 rb0 = *(float4*)&Bs[kk][tx * 8];
            float4 rb1 = *(float4*)&Bs[kk][tx * 8 + 4];
            float ra[8] = {ra0.x, ra0.y, ra0.z, ra0.w, ra1.x, ra1.y, ra1.z, ra1.w};
            float rb[8] = {rb0.x, rb0.y, rb0.z, rb0.w, rb1.x, rb1.y, rb1.z, rb1.w};
            #pragma unroll
            for (int i = 0; i < 8; i++)
                #pragma unroll
                for (int j = 0; j < 8; j++) acc[i][j] += ra[i] * rb[j];
        }
        __syncthreads();
    }
    #pragma unroll
    for (int i = 0; i < 8; i++) {
        int gm = bm + ty * 8 + i;
        #pragma unroll
        for (int j = 0; j < 8; j++) {
            int gn = bn + tx * 8 + j;
            if (gn < N) {
                float v = acc[i][j];
                if (addR) v += R[(size_t)gm * N + gn];
                C[(size_t)gm * N + gn] = v;
            }
        }
    }
}

// ------------------------- K3: causal depthwise conv + SiLU -------------------------
__global__ __launch_bounds__(256) void k_conv(const float* __restrict__ cw,
                                              const float* __restrict__ cb) {
    int c = blockIdx.x * 256 + threadIdx.x;
    int row = blockIdx.y;
    int s = row & (SEQ - 1);
    float w0 = cw[c * 4 + 0], w1 = cw[c * 4 + 1], w2 = cw[c * 4 + 2], w3 = cw[c * 4 + 3];
    const float* xp = g_proj + (size_t)row * PROJ + OFF_X + c;
    float acc = cb[c] + w3 * xp[0];
    if (s >= 1) acc += w2 * xp[-(int)PROJ];
    if (s >= 2) acc += w1 * xp[-2 * (int)PROJ];
    if (s >= 3) acc += w0 * xp[-3 * (int)PROJ];
    g_x[(size_t)row * DI + c] = acc / (1.f + expf(-acc));
}

// ------------------------- K3b: dt = mean_p softplus(dt_raw@w_dt + b_dt) -------------------------
__global__ __launch_bounds__(256) void k_dt(const float* __restrict__ wdt,
                                            const float* __restrict__ bdt) {
    int row = blockIdx.x, tid = threadIdx.x;
    int h = tid >> 5, lane = tid & 31;
    const float* pr = g_proj + (size_t)row * PROJ + OFF_DT;
    float dtr[8];
    #pragma unroll
    for (int j = 0; j < 8; j++) dtr[j] = pr[j];
    float acc = 0.f;
    #pragma unroll
    for (int q = 0; q < 8; q++) {
        int d = h * HD + lane * 8 + q;
        float v = bdt[d];
        #pragma unroll
        for (int j = 0; j < 8; j++) v += dtr[j] * wdt[j * DI + d];
        acc += (v > 20.f) ? v : log1pf(expf(v));
    }
    #pragma unroll
    for (int o = 16; o > 0; o >>= 1) acc += __shfl_xor_sync(0xffffffffu, acc, o);
    if (lane == 0) g_dt[row * NH + h] = acc * (1.0f / HD);
}

// ------------------------- K4a: per-chunk decay terms + masked Gram GM -------------------------
__global__ __launch_bounds__(256) void k_chunkprep(const float* __restrict__ A_log) {
    int c = blockIdx.x, h = blockIdx.y, b = blockIdx.z;
    int bhc = (b * NH + h) * NC + c;
    int rbase = b * SEQ + c * CHK;
    __shared__ float Bc[64 * 68];
    __shared__ float Cc[64 * 68];
    __shared__ float lcs[64];
    __shared__ float sdt[64];
    int tid = threadIdx.x;
    float A = -expf(A_log[h]);
    if (tid < 64) sdt[tid] = g_dt[(rbase + tid) * NH + h] * A;
    #pragma unroll
    for (int i = 0; i < 4; i++) {
        int f = (tid + 256 * i) * 4;
        int l = f >> 6, n = f & 63;
        const float* pr = g_proj + (size_t)(rbase + l) * PROJ;
        float4 bv = *(const float4*)(pr + OFF_B + h * NS + n);
        float4 cv = *(const float4*)(pr + OFF_C + h * NS + n);
        Bc[l * 68 + n + 0] = bv.x; Bc[l * 68 + n + 1] = bv.y;
        Bc[l * 68 + n + 2] = bv.z; Bc[l * 68 + n + 3] = bv.w;
        Cc[l * 68 + n + 0] = cv.x; Cc[l * 68 + n + 1] = cv.y;
        Cc[l * 68 + n + 2] = cv.z; Cc[l * 68 + n + 3] = cv.w;
    }
    __syncthreads();
    if (tid == 0) {
        float run = 0.f;
        for (int l = 0; l < 64; l++) { run += sdt[l]; lcs[l] = run; }
    }
    __syncthreads();
    float lcs63 = lcs[63];
    int l = tid >> 2, i0 = (tid & 3) * 16;
    float* outp = g_GM + (size_t)bhc * 4096;
    float myl = lcs[l];
    for (int q = 0; q < 16; q++) {
        int i = i0 + q;
        float g = 0.f;
        #pragma unroll
        for (int n = 0; n < 64; n++) g += Cc[l * 68 + n] * Bc[i * 68 + n];
        float m = (i <= l) ? expf(myl - lcs[i]) : 0.f;
        outp[l * 64 + i] = m * g;
    }
    if (tid < 64) {
        g_lcse[bhc * 64 + tid] = expf(lcs[tid]);
        g_wl[bhc * 64 + tid] = expf(lcs63 - lcs[tid]);
    }
    if (tid == 0) g_decay[bhc] = expf(lcs63);
}

// ------------------------- K4b: sequential chunk scan -------------------------
// grid (8 p-tiles, 8 heads, 2 batch); each block owns h-state [32p x 64n] in smem.
__global__ __launch_bounds__(256) void k_scan() {
    extern __shared__ float sm[];
    float* GMs = sm;              // 4096
    float* CBs = sm + 4096;       // 4096 (Ce in phase1, Bc in phase2)
    float* xcs = sm + 8192;       // 2048  x[l][p]
    float* hs  = sm + 10240;      // 64*33 = 2112  h[n][p]
    float* wls = sm + 12352;      // 64
    int tid = threadIdx.x;
    int pt = blockIdx.x, h = blockIdx.y, b = blockIdx.z;
    int p0 = pt * 32;
    int bh = b * NH + h;
    for (int e = tid; e < 2112; e += 256) hs[e] = 0.f;
    int lgrp = tid >> 4;          // 0..15
    int pp = (tid & 15) * 2;      // 0..30 step 2
    int lb = lgrp * 4;

    for (int c = 0; c < NC; c++) {
        int bhc = bh * NC + c;
        int rbase = b * SEQ + c * CHK;
        __syncthreads();
        // ---- loads ----
        const float* gmp = g_GM + (size_t)bhc * 4096;
        #pragma unroll
        for (int i = 0; i < 4; i++) {
            int f4 = (tid + 256 * i) * 4;
            *(float4*)&GMs[f4] = *(const float4*)&gmp[f4];
            int l = f4 >> 6, n = f4 & 63;
            float4 cv = *(const float4*)(g_proj + (size_t)(rbase + l) * PROJ + OFF_C + h * NS + n);
            float sc = g_lcse[bhc * 64 + l];
            cv.x *= sc; cv.y *= sc; cv.z *= sc; cv.w *= sc;
            *(float4*)&CBs[f4] = cv;
        }
        {
            int lr = tid >> 5, p = tid & 31;
            #pragma unroll
            for (int k = 0; k < 8; k++) {
                int l = lr * 8 + k;
                xcs[l * 32 + p] = g_x[(size_t)(rbase + l) * DI + h * HD + p0 + p];
            }
        }
        if (tid < 64) wls[tid] = g_wl[bhc * 64 + tid];
        float decay = g_decay[bhc];
        __syncthreads();
        // ---- phase1: out[l][p] = GM@x + Ce@h^T (uses OLD h) ----
        float a[4][2];
        #pragma unroll
        for (int li = 0; li < 4; li++) { a[li][0] = 0.f; a[li][1] = 0.f; }
        #pragma unroll 8
        for (int i = 0; i < 64; i++) {
            float xa = xcs[i * 32 + pp], xb = xcs[i * 32 + pp + 1];
            #pragma unroll
            for (int li = 0; li < 4; li++) {
                float g = GMs[(lb + li) * 64 + i];
                a[li][0] += g * xa; a[li][1] += g * xb;
            }
        }
        #pragma unroll 8
        for (int n = 0; n < 64; n++) {
            float ha = hs[n * 33 + pp], hb = hs[n * 33 + pp + 1];
            #pragma unroll
            for (int li = 0; li < 4; li++) {
                float ce = CBs[(lb + li) * 64 + n];
                a[li][0] += ce * ha; a[li][1] += ce * hb;
            }
        }
        #pragma unroll
        for (int li = 0; li < 4; li++) {
            float* yo = g_y + (size_t)(rbase + lb + li) * DI + h * HD + p0 + pp;
            yo[0] = a[li][0]; yo[1] = a[li][1];
        }
        __syncthreads();
        // ---- phase2a: xc *= wlast ; load Bc into CBs ----
        for (int e = tid; e < 2048; e += 256) { int l = e >> 5; xcs[e] *= wls[l]; }
        #pragma unroll
        for (int i = 0; i < 4; i++) {
            int f4 = (tid + 256 * i) * 4;
            int l = f4 >> 6, n = f4 & 63;
            *(float4*)&CBs[f4] =
                *(const float4*)(g_proj + (size_t)(rbase + l) * PROJ + OFF_B + h * NS + n);
        }
        __syncthreads();
        // ---- phase2c: h[n][p] = decay*h + sum_l (wl*x)[l][p] * B[l][n] ----
        int nb = lgrp * 4;
        float f[4][2];
        #pragma unroll
        for (int ni = 0; ni < 4; ni++) {
            f[ni][0] = decay * hs[(nb + ni) * 33 + pp];
            f[ni][1] = decay * hs[(nb + ni) * 33 + pp + 1];
        }
        #pragma unroll 8
        for (int l = 0; l < 64; l++) {
            float xa = xcs[l * 32 + pp], xb = xcs[l * 32 + pp + 1];
            float4 bv = *(float4*)&CBs[l * 64 + nb];
            f[0][0] += bv.x * xa; f[0][1] += bv.x * xb;
            f[1][0] += bv.y * xa; f[1][1] += bv.y * xb;
            f[2][0] += bv.z * xa; f[2][1] += bv.z * xb;
            f[3][0] += bv.w * xa; f[3][1] += bv.w * xb;
        }
        #pragma unroll
        for (int ni = 0; ni < 4; ni++) {
            hs[(nb + ni) * 33 + pp] = f[ni][0];
            hs[(nb + ni) * 33 + pp + 1] = f[ni][1];
        }
    }
}

// ------------------------- K5: y = (y + x*D)*silu(z), RMSNorm -------------------------
__global__ __launch_bounds__(256) void k_gate(const float* __restrict__ Dp,
                                              const float* __restrict__ wno) {
    int row = blockIdx.x, tid = threadIdx.x;
    __shared__ float red[8];
    const float* yr = g_y + (size_t)row * DI;
    const float* xr = g_x + (size_t)row * DI;
    const float* zr = g_proj + (size_t)row * PROJ + OFF_Z;
    float vals[8];
    float ss = 0.f;
    #pragma unroll
    for (int k = 0; k < 8; k++) {
        int cidx = tid + 256 * k;
        int hh = cidx >> 8;
        float y = yr[cidx] + xr[cidx] * Dp[hh];
        float z = zr[cidx];
        float v = y * (z / (1.f + expf(-z)));
        vals[k] = v; ss += v * v;
    }
    ss = blk_reduce_sum(ss, red);
    float sc = rsqrtf(ss * (1.0f / DI) + EPSV);
    float* outp = g_yn + (size_t)row * DI;
    #pragma unroll
    for (int k = 0; k < 8; k++) {
        int cidx = tid + 256 * k;
        outp[cidx] = vals[k] * sc * wno[cidx];
    }
}

// ------------------------- launch -------------------------
extern "C" void kernel_launch(void* const* d_in, const int* in_sizes, int n_in,
                              void* d_out, int out_size) {
    const float* hidden = (const float*)d_in[0];
    const float* w_norm_in = (const float*)d_in[1];
    const float* w_in_proj = (const float*)d_in[2];
    const float* conv_w = (const float*)d_in[3];
    const float* conv_b = (const float*)d_in[4];
    const float* w_dt = (const float*)d_in[5];
    const float* b_dt = (const float*)d_in[6];
    const float* A_log = (const float*)d_in[7];
    const float* Dp = (const float*)d_in[8];
    const float* w_norm_out = (const float*)d_in[9];
    const float* w_out_proj = (const float*)d_in[10];
    float* out = (float*)d_out;

    float *p_normed, *p_proj, *p_yn;
    cudaGetSymbolAddress((void**)&p_normed, g_normed);
    cudaGetSymbolAddress((void**)&p_proj, g_proj);
    cudaGetSymbolAddress((void**)&p_yn, g_yn);

    static int smem_set = 0;
    if (!smem_set) {
        cudaFuncSetAttribute(k_scan, cudaFuncAttributeMaxDynamicSharedMemorySize, 50176);
        smem_set = 1;
    }

    k_rms_in<<<ROWS, 256>>>(hidden, w_norm_in);
    sgemm<<<dim3((PROJ + 127) / 128, ROWS / 128), 256>>>(p_normed, w_in_proj, nullptr,
                                                         p_proj, ROWS, PROJ, DM, 0);
    k_conv<<<dim3(DI / 256, ROWS), 256>>>(conv_w, conv_b);
    k_dt<<<ROWS, 256>>>(w_dt, b_dt);
    k_chunkprep<<<dim3(NC, NH, 2), 256>>>(A_log);
    k_scan<<<dim3(8, NH, 2), 256, 49664>>>();
    k_gate<<<ROWS, 256>>>(Dp, w_norm_out);
    sgemm<<<dim3(DM / 128, ROWS / 128), 256>>>(p_yn, w_out_proj, hidden,
                                               out, ROWS, DM, DI, 1);
}

// round 3
// speedup vs baseline: 2.0069x; 2.0069x over previous
#include <cuda_runtime.h>
#include <cstdint>
#include <math.h>

#define ROWS   8192
#define SEQ    4096
#define DM     1024
#define DI     2048
#define NH     8
#define HD     256
#define NS     64
#define CHK    64
#define NC     64
#define PROJ   5128
#define OFF_Z  0
#define OFF_X  2048
#define OFF_B  4096
#define OFF_C  4608
#define OFF_DT 5120
#define EPSV   1.1920929e-7f

// ------------------------- scratch (device globals) -------------------------
__device__ float g_normed[ROWS * DM];
__device__ float g_proj[(size_t)ROWS * PROJ];
__device__ float g_x[ROWS * DI];
__device__ float g_dt[ROWS * NH];
__device__ float g_GM[1024 * 4096];
__device__ float g_lcse[1024 * 64];
__device__ float g_wl[1024 * 64];
__device__ float g_decay[1024];
__device__ float g_y[ROWS * DI];
__device__ float g_yn[ROWS * DI];

// ------------------------- helpers -------------------------
__device__ __forceinline__ float blk_reduce_sum(float v, float* red) {
    int tid = threadIdx.x;
    #pragma unroll
    for (int o = 16; o > 0; o >>= 1) v += __shfl_xor_sync(0xffffffffu, v, o);
    if ((tid & 31) == 0) red[tid >> 5] = v;
    __syncthreads();
    if (tid < 8) {
        float t = red[tid];
        #pragma unroll
        for (int o = 4; o > 0; o >>= 1) t += __shfl_xor_sync(0xffu, t, o);
        if (tid == 0) red[0] = t;
    }
    __syncthreads();
    return red[0];
}

__device__ __forceinline__ uint32_t f2tf(float f) {
    uint32_t o;
    asm("cvt.rna.tf32.f32 %0, %1;" : "=r"(o) : "f"(f));
    return o;
}

__device__ __forceinline__ void cp16(void* dst, const void* src, int pred) {
    uint32_t d = (uint32_t)__cvta_generic_to_shared(dst);
    int sz = pred ? 16 : 0;
    asm volatile("cp.async.cg.shared.global [%0], [%1], 16, %2;\n"
                 :: "r"(d), "l"(src), "r"(sz));
}
__device__ __forceinline__ void cp_commit() {
    asm volatile("cp.async.commit_group;\n" ::);
}
template <int N>
__device__ __forceinline__ void cp_wait() {
    asm volatile("cp.async.wait_group %0;\n" :: "n"(N));
}

__device__ __forceinline__ void mma8(float* c, const uint32_t* a, const uint32_t* b) {
    asm volatile(
        "mma.sync.aligned.m16n8k8.row.col.f32.tf32.tf32.f32 "
        "{%0,%1,%2,%3},{%4,%5,%6,%7},{%8,%9},{%0,%1,%2,%3};\n"
        : "+f"(c[0]), "+f"(c[1]), "+f"(c[2]), "+f"(c[3])
        : "r"(a[0]), "r"(a[1]), "r"(a[2]), "r"(a[3]), "r"(b[0]), "r"(b[1]));
}

// ------------------------- K1: input RMSNorm -------------------------
__global__ __launch_bounds__(256) void k_rms_in(const float* __restrict__ hidden,
                                                const float* __restrict__ w) {
    int row = blockIdx.x, tid = threadIdx.x;
    __shared__ float red[8];
    float4 v = ((const float4*)(hidden + (size_t)row * DM))[tid];
    float ss = v.x * v.x + v.y * v.y + v.z * v.z + v.w * v.w;
    ss = blk_reduce_sum(ss, red);
    float sc = rsqrtf(ss * (1.0f / DM) + EPSV);
    float4 wv = ((const float4*)w)[tid];
    float4 o;
    o.x = v.x * sc * wv.x; o.y = v.y * sc * wv.y;
    o.z = v.z * sc * wv.z; o.w = v.w * sc * wv.w;
    ((float4*)(g_normed + (size_t)row * DM))[tid] = o;
}

// ------------------------- TF32 tensor-core GEMM -------------------------
// C[M,N] = A[M,K] @ B[K,N] (+R). BM=BN=128, BK=16, 128 threads (4 warps, 64x64 each).
#define ASTR 20
#define BSTR 136

__device__ __forceinline__ void g2s_stage(const float* __restrict__ A,
                                          const float* __restrict__ B,
                                          float* As_st, float* Bs_st,
                                          int bm, int bn, int k0, int N, int K,
                                          int tid) {
    const float* Ap = A + (size_t)(bm + tid) * K + k0;
    float* ap = As_st + tid * ASTR;
    #pragma unroll
    for (int i = 0; i < 4; i++) cp16(ap + i * 4, Ap + i * 4, 1);
    int br = tid >> 3, bc0 = (tid & 7) * 16;
    const float* Bp = B + (size_t)(k0 + br) * N + bn;
    float* bp = Bs_st + br * BSTR;
    #pragma unroll
    for (int i = 0; i < 4; i++) {
        int c = bc0 + i * 4;
        cp16(bp + c, Bp + c, (bn + c) < N ? 1 : 0);
    }
}

__global__ __launch_bounds__(128) void gemm_tc(const float* __restrict__ A,
                                               const float* __restrict__ B,
                                               const float* __restrict__ R,
                                               float* __restrict__ C,
                                               int M, int N, int K, int addR) {
    __shared__ float As[2][128 * ASTR];
    __shared__ float Bs[2][16 * BSTR];
    int tid = threadIdx.x, lane = tid & 31, warp = tid >> 5;
    int bm = blockIdx.y * 128, bn = blockIdx.x * 128;
    int wm = (warp >> 1) * 64, wn = (warp & 1) * 64;
    float acc[4][8][4];
    #pragma unroll
    for (int mi = 0; mi < 4; mi++)
        #pragma unroll
        for (int ni = 0; ni < 8; ni++)
            #pragma unroll
            for (int q = 0; q < 4; q++) acc[mi][ni][q] = 0.f;

    int nk = K / 16;
    g2s_stage(A, B, As[0], Bs[0], bm, bn, 0, N, K, tid);
    cp_commit();

    int r = lane >> 2, cc = lane & 3;
    for (int kb = 0; kb < nk; kb++) {
        int cur = kb & 1;
        if (kb + 1 < nk) {
            g2s_stage(A, B, As[cur ^ 1], Bs[cur ^ 1], bm, bn, (kb + 1) * 16, N, K, tid);
            cp_commit();
            cp_wait<1>();
        } else {
            cp_wait<0>();
        }
        __syncthreads();
        const float* Ac = As[cur];
        const float* Bc = Bs[cur];
        #pragma unroll
        for (int k8 = 0; k8 < 16; k8 += 8) {
            uint32_t af[4][4];
            #pragma unroll
            for (int mi = 0; mi < 4; mi++) {
                const float* p = Ac + (wm + mi * 16 + r) * ASTR + k8 + cc;
                af[mi][0] = f2tf(p[0]);
                af[mi][1] = f2tf(p[8 * ASTR]);
                af[mi][2] = f2tf(p[4]);
                af[mi][3] = f2tf(p[8 * ASTR + 4]);
            }
            uint32_t bf[8][2];
            #pragma unroll
            for (int ni = 0; ni < 8; ni++) {
                const float* q = Bc + (k8 + cc) * BSTR + wn + ni * 8 + r;
                bf[ni][0] = f2tf(q[0]);
                bf[ni][1] = f2tf(q[4 * BSTR]);
            }
            #pragma unroll
            for (int mi = 0; mi < 4; mi++)
                #pragma unroll
                for (int ni = 0; ni < 8; ni++)
                    mma8(acc[mi][ni], af[mi], bf[ni]);
        }
        __syncthreads();
    }

    #pragma unroll
    for (int mi = 0; mi < 4; mi++) {
        int row = bm + wm + mi * 16 + r;
        #pragma unroll
        for (int ni = 0; ni < 8; ni++) {
            int col = bn + wn + ni * 8 + 2 * cc;
            if (col < N) {
                size_t o0 = (size_t)row * N + col;
                size_t o1 = (size_t)(row + 8) * N + col;
                float2 v0 = make_float2(acc[mi][ni][0], acc[mi][ni][1]);
                float2 v1 = make_float2(acc[mi][ni][2], acc[mi][ni][3]);
                if (addR) {
                    float2 r0 = *(const float2*)(R + o0);
                    float2 r1 = *(const float2*)(R + o1);
                    v0.x += r0.x; v0.y += r0.y;
                    v1.x += r1.x; v1.y += r1.y;
                }
                *(float2*)(C + o0) = v0;
                *(float2*)(C + o1) = v1;
            }
        }
    }
}

// ------------------------- K3: causal depthwise conv + SiLU -------------------------
__global__ __launch_bounds__(256) void k_conv(const float* __restrict__ cw,
                                              const float* __restrict__ cb) {
    int c = blockIdx.x * 256 + threadIdx.x;
    int row = blockIdx.y;
    int s = row & (SEQ - 1);
    float w0 = cw[c * 4 + 0], w1 = cw[c * 4 + 1], w2 = cw[c * 4 + 2], w3 = cw[c * 4 + 3];
    const float* xp = g_proj + (size_t)row * PROJ + OFF_X + c;
    float acc = cb[c] + w3 * xp[0];
    if (s >= 1) acc += w2 * xp[-(int)PROJ];
    if (s >= 2) acc += w1 * xp[-2 * (int)PROJ];
    if (s >= 3) acc += w0 * xp[-3 * (int)PROJ];
    g_x[(size_t)row * DI + c] = acc / (1.f + expf(-acc));
}

// ------------------------- K3b: dt -------------------------
__global__ __launch_bounds__(256) void k_dt(const float* __restrict__ wdt,
                                            const float* __restrict__ bdt) {
    int tid = threadIdx.x;
    int h = tid >> 5, lane = tid & 31;
    int d0 = h * HD + lane * 8;
    float w[8][8], bb[8];
    #pragma unroll
    for (int j = 0; j < 8; j++)
        #pragma unroll
        for (int q = 0; q < 8; q++) w[j][q] = wdt[j * DI + d0 + q];
    #pragma unroll
    for (int q = 0; q < 8; q++) bb[q] = bdt[d0 + q];

    int row0 = blockIdx.x * 16;
    for (int rr = 0; rr < 16; rr++) {
        int row = row0 + rr;
        const float* pr = g_proj + (size_t)row * PROJ + OFF_DT;
        float dtr[8];
        #pragma unroll
        for (int j = 0; j < 8; j++) dtr[j] = pr[j];
        float acc = 0.f;
        #pragma unroll
        for (int q = 0; q < 8; q++) {
            float v = bb[q];
            #pragma unroll
            for (int j = 0; j < 8; j++) v += dtr[j] * w[j][q];
            acc += (v > 20.f) ? v : log1pf(expf(v));
        }
        #pragma unroll
        for (int o = 16; o > 0; o >>= 1) acc += __shfl_xor_sync(0xffffffffu, acc, o);
        if (lane == 0) g_dt[row * NH + h] = acc * (1.0f / HD);
    }
}

// ------------------------- K4a: chunk prep -------------------------
__global__ __launch_bounds__(256) void k_chunkprep(const float* __restrict__ A_log) {
    int c = blockIdx.x, h = blockIdx.y, b = blockIdx.z;
    int bhc = (b * NH + h) * NC + c;
    int rbase = b * SEQ + c * CHK;
    __shared__ float Bc[64 * 68];
    __shared__ float Cc[64 * 68];
    __shared__ float lcs[64];
    __shared__ float sdt[64];
    int tid = threadIdx.x;
    float A = -expf(A_log[h]);
    if (tid < 64) sdt[tid] = g_dt[(rbase + tid) * NH + h] * A;
    #pragma unroll
    for (int i = 0; i < 4; i++) {
        int f = (tid + 256 * i) * 4;
        int l = f >> 6, n = f & 63;
        const float* pr = g_proj + (size_t)(rbase + l) * PROJ;
        float4 bv = *(const float4*)(pr + OFF_B + h * NS + n);
        float4 cv = *(const float4*)(pr + OFF_C + h * NS + n);
        Bc[l * 68 + n + 0] = bv.x; Bc[l * 68 + n + 1] = bv.y;
        Bc[l * 68 + n + 2] = bv.z; Bc[l * 68 + n + 3] = bv.w;
        Cc[l * 68 + n + 0] = cv.x; Cc[l * 68 + n + 1] = cv.y;
        Cc[l * 68 + n + 2] = cv.z; Cc[l * 68 + n + 3] = cv.w;
    }
    __syncthreads();
    if (tid == 0) {
        float run = 0.f;
        for (int l = 0; l < 64; l++) { run += sdt[l]; lcs[l] = run; }
    }
    __syncthreads();
    float lcs63 = lcs[63];
    int l = tid >> 2, i0 = (tid & 3) * 16;
    float* outp = g_GM + (size_t)bhc * 4096;
    float myl = lcs[l];
    for (int q = 0; q < 16; q++) {
        int i = i0 + q;
        float g = 0.f;
        #pragma unroll
        for (int n = 0; n < 64; n++) g += Cc[l * 68 + n] * Bc[i * 68 + n];
        float m = (i <= l) ? expf(myl - lcs[i]) : 0.f;
        outp[l * 64 + i] = m * g;
    }
    if (tid < 64) {
        g_lcse[bhc * 64 + tid] = expf(lcs[tid]);
        g_wl[bhc * 64 + tid] = expf(lcs63 - lcs[tid]);
    }
    if (tid == 0) g_decay[bhc] = expf(lcs63);
}

// ------------------------- K4b: sequential chunk scan -------------------------
__global__ __launch_bounds__(256) void k_scan() {
    extern __shared__ float sm[];
    float* GMs = sm;
    float* CBs = sm + 4096;
    float* xcs = sm + 8192;
    float* hs  = sm + 10240;
    float* wls = sm + 12352;
    int tid = threadIdx.x;
    int pt = blockIdx.x, h = blockIdx.y, b = blockIdx.z;
    int p0 = pt * 32;
    int bh = b * NH + h;
    for (int e = tid; e < 2112; e += 256) hs[e] = 0.f;
    int lgrp = tid >> 4;
    int pp = (tid & 15) * 2;
    int lb = lgrp * 4;

    for (int c = 0; c < NC; c++) {
        int bhc = bh * NC + c;
        int rbase = b * SEQ + c * CHK;
        __syncthreads();
        const float* gmp = g_GM + (size_t)bhc * 4096;
        #pragma unroll
        for (int i = 0; i < 4; i++) {
            int f4 = (tid + 256 * i) * 4;
            *(float4*)&GMs[f4] = *(const float4*)&gmp[f4];
            int l = f4 >> 6, n = f4 & 63;
            float4 cv = *(const float4*)(g_proj + (size_t)(rbase + l) * PROJ + OFF_C + h * NS + n);
            float sc = g_lcse[bhc * 64 + l];
            cv.x *= sc; cv.y *= sc; cv.z *= sc; cv.w *= sc;
            *(float4*)&CBs[f4] = cv;
        }
        {
            int lr = tid >> 5, p = tid & 31;
            #pragma unroll
            for (int k = 0; k < 8; k++) {
                int l = lr * 8 + k;
                xcs[l * 32 + p] = g_x[(size_t)(rbase + l) * DI + h * HD + p0 + p];
            }
        }
        if (tid < 64) wls[tid] = g_wl[bhc * 64 + tid];
        float decay = g_decay[bhc];
        __syncthreads();
        float a[4][2];
        #pragma unroll
        for (int li = 0; li < 4; li++) { a[li][0] = 0.f; a[li][1] = 0.f; }
        #pragma unroll 8
        for (int i = 0; i < 64; i++) {
            float xa = xcs[i * 32 + pp], xb = xcs[i * 32 + pp + 1];
            #pragma unroll
            for (int li = 0; li < 4; li++) {
                float g = GMs[(lb + li) * 64 + i];
                a[li][0] += g * xa; a[li][1] += g * xb;
            }
        }
        #pragma unroll 8
        for (int n = 0; n < 64; n++) {
            float ha = hs[n * 33 + pp], hb = hs[n * 33 + pp + 1];
            #pragma unroll
            for (int li = 0; li < 4; li++) {
                float ce = CBs[(lb + li) * 64 + n];
                a[li][0] += ce * ha; a[li][1] += ce * hb;
            }
        }
        #pragma unroll
        for (int li = 0; li < 4; li++) {
            float* yo = g_y + (size_t)(rbase + lb + li) * DI + h * HD + p0 + pp;
            yo[0] = a[li][0]; yo[1] = a[li][1];
        }
        __syncthreads();
        for (int e = tid; e < 2048; e += 256) { int l = e >> 5; xcs[e] *= wls[l]; }
        #pragma unroll
        for (int i = 0; i < 4; i++) {
            int f4 = (tid + 256 * i) * 4;
            int l = f4 >> 6, n = f4 & 63;
            *(float4*)&CBs[f4] =
                *(const float4*)(g_proj + (size_t)(rbase + l) * PROJ + OFF_B + h * NS + n);
        }
        __syncthreads();
        int nb = lgrp * 4;
        float f[4][2];
        #pragma unroll
        for (int ni = 0; ni < 4; ni++) {
            f[ni][0] = decay * hs[(nb + ni) * 33 + pp];
            f[ni][1] = decay * hs[(nb + ni) * 33 + pp + 1];
        }
        #pragma unroll 8
        for (int l = 0; l < 64; l++) {
            float xa = xcs[l * 32 + pp], xb = xcs[l * 32 + pp + 1];
            float4 bv = *(float4*)&CBs[l * 64 + nb];
            f[0][0] += bv.x * xa; f[0][1] += bv.x * xb;
            f[1][0] += bv.y * xa; f[1][1] += bv.y * xb;
            f[2][0] += bv.z * xa; f[2][1] += bv.z * xb;
            f[3][0] += bv.w * xa; f[3][1] += bv.w * xb;
        }
        #pragma unroll
        for (int ni = 0; ni < 4; ni++) {
            hs[(nb + ni) * 33 + pp] = f[ni][0];
            hs[(nb + ni) * 33 + pp + 1] = f[ni][1];
        }
    }
}

// ------------------------- K5: gate + RMSNorm -------------------------
__global__ __launch_bounds__(256) void k_gate(const float* __restrict__ Dp,
                                              const float* __restrict__ wno) {
    int row = blockIdx.x, tid = threadIdx.x;
    __shared__ float red[8];
    const float* yr = g_y + (size_t)row * DI;
    const float* xr = g_x + (size_t)row * DI;
    const float* zr = g_proj + (size_t)row * PROJ + OFF_Z;
    float vals[8];
    float ss = 0.f;
    #pragma unroll
    for (int k = 0; k < 8; k++) {
        int cidx = tid + 256 * k;
        int hh = cidx >> 8;
        float y = yr[cidx] + xr[cidx] * Dp[hh];
        float z = zr[cidx];
        float v = y * (z / (1.f + expf(-z)));
        vals[k] = v; ss += v * v;
    }
    ss = blk_reduce_sum(ss, red);
    float sc = rsqrtf(ss * (1.0f / DI) + EPSV);
    float* outp = g_yn + (size_t)row * DI;
    #pragma unroll
    for (int k = 0; k < 8; k++) {
        int cidx = tid + 256 * k;
        outp[cidx] = vals[k] * sc * wno[cidx];
    }
}

// ------------------------- launch -------------------------
extern "C" void kernel_launch(void* const* d_in, const int* in_sizes, int n_in,
                              void* d_out, int out_size) {
    const float* hidden = (const float*)d_in[0];
    const float* w_norm_in = (const float*)d_in[1];
    const float* w_in_proj = (const float*)d_in[2];
    const float* conv_w = (const float*)d_in[3];
    const float* conv_b = (const float*)d_in[4];
    const float* w_dt = (const float*)d_in[5];
    const float* b_dt = (const float*)d_in[6];
    const float* A_log = (const float*)d_in[7];
    const float* Dp = (const float*)d_in[8];
    const float* w_norm_out = (const float*)d_in[9];
    const float* w_out_proj = (const float*)d_in[10];
    float* out = (float*)d_out;

    float *p_normed, *p_proj, *p_yn;
    cudaGetSymbolAddress((void**)&p_normed, g_normed);
    cudaGetSymbolAddress((void**)&p_proj, g_proj);
    cudaGetSymbolAddress((void**)&p_yn, g_yn);

    cudaFuncSetAttribute(k_scan, cudaFuncAttributeMaxDynamicSharedMemorySize, 50176);

    k_rms_in<<<ROWS, 256>>>(hidden, w_norm_in);
    gemm_tc<<<dim3((PROJ + 127) / 128, ROWS / 128), 128>>>(p_normed, w_in_proj, nullptr,
                                                           p_proj, ROWS, PROJ, DM, 0);
    k_conv<<<dim3(DI / 256, ROWS), 256>>>(conv_w, conv_b);
    k_dt<<<ROWS / 16, 256>>>(w_dt, b_dt);
    k_chunkprep<<<dim3(NC, NH, 2), 256>>>(A_log);
    k_scan<<<dim3(8, NH, 2), 256, 49664>>>();
    k_gate<<<ROWS, 256>>>(Dp, w_norm_out);
    gemm_tc<<<dim3(DM / 128, ROWS / 128), 128>>>(p_yn, w_out_proj, hidden,
                                                 out, ROWS, DM, DI, 1);
}

// round 4
// speedup vs baseline: 2.0930x; 1.0429x over previous
#include <cuda_runtime.h>
#include <cstdint>
#include <math.h>

#define ROWS   8192
#define SEQ    4096
#define DM     1024
#define DI     2048
#define NH     8
#define HD     256
#define NS     64
#define CHK    64
#define NC     64
#define PROJ   5128
#define OFF_Z  0
#define OFF_X  2048
#define OFF_B  4096
#define OFF_C  4608
#define OFF_DT 5120
#define EPSV   1.1920929e-7f

// ------------------------- scratch (device globals) -------------------------
__device__ float g_normed[ROWS * DM];              // tf32-rounded
__device__ float g_proj[(size_t)ROWS * PROJ];
__device__ float g_x[ROWS * DI];
__device__ float g_dt[ROWS * NH];
__device__ float g_GM[1024 * 4096];
__device__ float g_lcse[1024 * 64];
__device__ float g_wl[1024 * 64];
__device__ float g_decay[1024];
__device__ float g_y[ROWS * DI];
__device__ float g_yn[ROWS * DI];                  // tf32-rounded
__device__ float g_w1t[DM * PROJ];                 // tf32-rounded w_in_proj
__device__ float g_w2t[DI * DM];                   // tf32-rounded w_out_proj

// ------------------------- helpers -------------------------
__device__ __forceinline__ float blk_reduce_sum(float v, float* red) {
    int tid = threadIdx.x;
    #pragma unroll
    for (int o = 16; o > 0; o >>= 1) v += __shfl_xor_sync(0xffffffffu, v, o);
    if ((tid & 31) == 0) red[tid >> 5] = v;
    __syncthreads();
    if (tid < 8) {
        float t = red[tid];
        #pragma unroll
        for (int o = 4; o > 0; o >>= 1) t += __shfl_xor_sync(0xffu, t, o);
        if (tid == 0) red[0] = t;
    }
    __syncthreads();
    return red[0];
}

__device__ __forceinline__ float f2tf_f(float f) {
    uint32_t o;
    asm("cvt.rna.tf32.f32 %0, %1;" : "=r"(o) : "f"(f));
    return __uint_as_float(o);
}

__device__ __forceinline__ void cp16(void* dst, const void* src, int pred) {
    uint32_t d = (uint32_t)__cvta_generic_to_shared(dst);
    int sz = pred ? 16 : 0;
    asm volatile("cp.async.cg.shared.global [%0], [%1], 16, %2;\n"
                 :: "r"(d), "l"(src), "r"(sz));
}
__device__ __forceinline__ void cp_commit() {
    asm volatile("cp.async.commit_group;\n" ::);
}
template <int N>
__device__ __forceinline__ void cp_wait() {
    asm volatile("cp.async.wait_group %0;\n" :: "n"(N));
}

__device__ __forceinline__ void mma8(float* c, const uint32_t* a, const uint32_t* b) {
    asm volatile(
        "mma.sync.aligned.m16n8k8.row.col.f32.tf32.tf32.f32 "
        "{%0,%1,%2,%3},{%4,%5,%6,%7},{%8,%9},{%0,%1,%2,%3};\n"
        : "+f"(c[0]), "+f"(c[1]), "+f"(c[2]), "+f"(c[3])
        : "r"(a[0]), "r"(a[1]), "r"(a[2]), "r"(a[3]), "r"(b[0]), "r"(b[1]));
}

// ------------------------- K0: weight -> tf32 rounding -------------------------
__global__ __launch_bounds__(256) void k_cvt(const float* __restrict__ in,
                                             float* __restrict__ out, int n4) {
    int i = blockIdx.x * 256 + threadIdx.x;
    if (i < n4) {
        float4 v = ((const float4*)in)[i];
        v.x = f2tf_f(v.x); v.y = f2tf_f(v.y); v.z = f2tf_f(v.z); v.w = f2tf_f(v.w);
        ((float4*)out)[i] = v;
    }
}

// ------------------------- K1: input RMSNorm (tf32-rounded output) -------------------------
__global__ __launch_bounds__(256) void k_rms_in(const float* __restrict__ hidden,
                                                const float* __restrict__ w) {
    int row = blockIdx.x, tid = threadIdx.x;
    __shared__ float red[8];
    float4 v = ((const float4*)(hidden + (size_t)row * DM))[tid];
    float ss = v.x * v.x + v.y * v.y + v.z * v.z + v.w * v.w;
    ss = blk_reduce_sum(ss, red);
    float sc = rsqrtf(ss * (1.0f / DM) + EPSV);
    float4 wv = ((const float4*)w)[tid];
    float4 o;
    o.x = f2tf_f(v.x * sc * wv.x); o.y = f2tf_f(v.y * sc * wv.y);
    o.z = f2tf_f(v.z * sc * wv.z); o.w = f2tf_f(v.w * sc * wv.w);
    ((float4*)(g_normed + (size_t)row * DM))[tid] = o;
}

// ------------------------- TF32 tensor-core GEMM -------------------------
// C[M,N] = A[M,K] @ B[K,N] (+R). BM=256, BN=128, BK=16, 256 thr (8 warps, 64x64).
// A and B must already be tf32-rounded.
#define ASTR 20
#define BSTR 136
#define A_ST (256 * ASTR)
#define B_ST (16 * BSTR)

__device__ __forceinline__ void g2s_stage(const float* __restrict__ A,
                                          const float* __restrict__ B,
                                          float* As_st, float* Bs_st,
                                          int bm, int bn, int k0, int N, int K,
                                          int tid) {
    const float* Ap = A + (size_t)(bm + tid) * K + k0;
    float* ap = As_st + tid * ASTR;
    #pragma unroll
    for (int i = 0; i < 4; i++) cp16(ap + i * 4, Ap + i * 4, 1);
    int br = tid >> 4, bc0 = (tid & 15) * 8;
    const float* Bp = B + (size_t)(k0 + br) * N + bn;
    float* bp = Bs_st + br * BSTR;
    #pragma unroll
    for (int i = 0; i < 2; i++) {
        int c = bc0 + i * 4;
        cp16(bp + c, Bp + c, (bn + c) < N ? 1 : 0);
    }
}

__global__ __launch_bounds__(256) void gemm_tc(const float* __restrict__ A,
                                               const float* __restrict__ B,
                                               const float* __restrict__ R,
                                               float* __restrict__ C,
                                               int M, int N, int K, int addR) {
    extern __shared__ float smd[];
    float* As = smd;                 // 2 stages of 256*ASTR
    float* Bs = smd + 2 * A_ST;      // 2 stages of 16*BSTR
    int tid = threadIdx.x, lane = tid & 31, warp = tid >> 5;
    int bm = blockIdx.y * 256, bn = blockIdx.x * 128;
    int wm = (warp >> 1) * 64, wn = (warp & 1) * 64;
    float acc[4][8][4];
    #pragma unroll
    for (int mi = 0; mi < 4; mi++)
        #pragma unroll
        for (int ni = 0; ni < 8; ni++)
            #pragma unroll
            for (int q = 0; q < 4; q++) acc[mi][ni][q] = 0.f;

    int nk = K / 16;
    g2s_stage(A, B, As, Bs, bm, bn, 0, N, K, tid);
    cp_commit();

    int r = lane >> 2, cc = lane & 3;
    for (int kb = 0; kb < nk; kb++) {
        int cur = kb & 1;
        if (kb + 1 < nk) {
            g2s_stage(A, B, As + (cur ^ 1) * A_ST, Bs + (cur ^ 1) * B_ST,
                      bm, bn, (kb + 1) * 16, N, K, tid);
            cp_commit();
            cp_wait<1>();
        } else {
            cp_wait<0>();
        }
        __syncthreads();
        const float* Ac = As + cur * A_ST;
        const float* Bc = Bs + cur * B_ST;
        #pragma unroll
        for (int k8 = 0; k8 < 16; k8 += 8) {
            uint32_t af[4][4];
            #pragma unroll
            for (int mi = 0; mi < 4; mi++) {
                const float* p = Ac + (wm + mi * 16 + r) * ASTR + k8 + cc;
                af[mi][0] = __float_as_uint(p[0]);
                af[mi][1] = __float_as_uint(p[8 * ASTR]);
                af[mi][2] = __float_as_uint(p[4]);
                af[mi][3] = __float_as_uint(p[8 * ASTR + 4]);
            }
            uint32_t bf[8][2];
            #pragma unroll
            for (int ni = 0; ni < 8; ni++) {
                const float* q = Bc + (k8 + cc) * BSTR + wn + ni * 8 + r;
                bf[ni][0] = __float_as_uint(q[0]);
                bf[ni][1] = __float_as_uint(q[4 * BSTR]);
            }
            #pragma unroll
            for (int mi = 0; mi < 4; mi++)
                #pragma unroll
                for (int ni = 0; ni < 8; ni++)
                    mma8(acc[mi][ni], af[mi], bf[ni]);
        }
        __syncthreads();
    }

    #pragma unroll
    for (int mi = 0; mi < 4; mi++) {
        int row = bm + wm + mi * 16 + r;
        #pragma unroll
        for (int ni = 0; ni < 8; ni++) {
            int col = bn + wn + ni * 8 + 2 * cc;
            if (col < N) {
                size_t o0 = (size_t)row * N + col;
                size_t o1 = (size_t)(row + 8) * N + col;
                float2 v0 = make_float2(acc[mi][ni][0], acc[mi][ni][1]);
                float2 v1 = make_float2(acc[mi][ni][2], acc[mi][ni][3]);
                if (addR) {
                    float2 r0 = *(const float2*)(R + o0);
                    float2 r1 = *(const float2*)(R + o1);
                    v0.x += r0.x; v0.y += r0.y;
                    v1.x += r1.x; v1.y += r1.y;
                }
                *(float2*)(C + o0) = v0;
                *(float2*)(C + o1) = v1;
            }
        }
    }
}

// ------------------------- K3: causal depthwise conv + SiLU -------------------------
__global__ __launch_bounds__(256) void k_conv(const float* __restrict__ cw,
                                              const float* __restrict__ cb) {
    int c = blockIdx.x * 256 + threadIdx.x;
    int row = blockIdx.y;
    int s = row & (SEQ - 1);
    float w0 = cw[c * 4 + 0], w1 = cw[c * 4 + 1], w2 = cw[c * 4 + 2], w3 = cw[c * 4 + 3];
    const float* xp = g_proj + (size_t)row * PROJ + OFF_X + c;
    float acc = cb[c] + w3 * xp[0];
    if (s >= 1) acc += w2 * xp[-(int)PROJ];
    if (s >= 2) acc += w1 * xp[-2 * (int)PROJ];
    if (s >= 3) acc += w0 * xp[-3 * (int)PROJ];
    g_x[(size_t)row * DI + c] = acc / (1.f + expf(-acc));
}

// ------------------------- K3b: dt -------------------------
__global__ __launch_bounds__(256) void k_dt(const float* __restrict__ wdt,
                                            const float* __restrict__ bdt) {
    int tid = threadIdx.x;
    int h = tid >> 5, lane = tid & 31;
    int d0 = h * HD + lane * 8;
    float w[8][8], bb[8];
    #pragma unroll
    for (int j = 0; j < 8; j++)
        #pragma unroll
        for (int q = 0; q < 8; q++) w[j][q] = wdt[j * DI + d0 + q];
    #pragma unroll
    for (int q = 0; q < 8; q++) bb[q] = bdt[d0 + q];

    int row0 = blockIdx.x * 16;
    for (int rr = 0; rr < 16; rr++) {
        int row = row0 + rr;
        const float* pr = g_proj + (size_t)row * PROJ + OFF_DT;
        float dtr[8];
        #pragma unroll
        for (int j = 0; j < 8; j++) dtr[j] = pr[j];
        float acc = 0.f;
        #pragma unroll
        for (int q = 0; q < 8; q++) {
            float v = bb[q];
            #pragma unroll
            for (int j = 0; j < 8; j++) v += dtr[j] * w[j][q];
            acc += (v > 20.f) ? v : log1pf(expf(v));
        }
        #pragma unroll
        for (int o = 16; o > 0; o >>= 1) acc += __shfl_xor_sync(0xffffffffu, acc, o);
        if (lane == 0) g_dt[row * NH + h] = acc * (1.0f / HD);
    }
}

// ------------------------- K4a: chunk prep -------------------------
__global__ __launch_bounds__(256) void k_chunkprep(const float* __restrict__ A_log) {
    int c = blockIdx.x, h = blockIdx.y, b = blockIdx.z;
    int bhc = (b * NH + h) * NC + c;
    int rbase = b * SEQ + c * CHK;
    __shared__ float Bc[64 * 68];
    __shared__ float Cc[64 * 68];
    __shared__ float lcs[64];
    __shared__ float sdt[64];
    int tid = threadIdx.x;
    float A = -expf(A_log[h]);
    if (tid < 64) sdt[tid] = g_dt[(rbase + tid) * NH + h] * A;
    #pragma unroll
    for (int i = 0; i < 4; i++) {
        int f = (tid + 256 * i) * 4;
        int l = f >> 6, n = f & 63;
        const float* pr = g_proj + (size_t)(rbase + l) * PROJ;
        float4 bv = *(const float4*)(pr + OFF_B + h * NS + n);
        float4 cv = *(const float4*)(pr + OFF_C + h * NS + n);
        Bc[l * 68 + n + 0] = bv.x; Bc[l * 68 + n + 1] = bv.y;
        Bc[l * 68 + n + 2] = bv.z; Bc[l * 68 + n + 3] = bv.w;
        Cc[l * 68 + n + 0] = cv.x; Cc[l * 68 + n + 1] = cv.y;
        Cc[l * 68 + n + 2] = cv.z; Cc[l * 68 + n + 3] = cv.w;
    }
    __syncthreads();
    if (tid == 0) {
        float run = 0.f;
        for (int l = 0; l < 64; l++) { run += sdt[l]; lcs[l] = run; }
    }
    __syncthreads();
    float lcs63 = lcs[63];
    int l = tid >> 2, i0 = (tid & 3) * 16;
    float* outp = g_GM + (size_t)bhc * 4096;
    float myl = lcs[l];
    for (int q = 0; q < 16; q++) {
        int i = i0 + q;
        float g = 0.f;
        #pragma unroll
        for (int n = 0; n < 64; n++) g += Cc[l * 68 + n] * Bc[i * 68 + n];
        float m = (i <= l) ? expf(myl - lcs[i]) : 0.f;
        outp[l * 64 + i] = m * g;
    }
    if (tid < 64) {
        g_lcse[bhc * 64 + tid] = expf(lcs[tid]);
        g_wl[bhc * 64 + tid] = expf(lcs63 - lcs[tid]);
    }
    if (tid == 0) g_decay[bhc] = expf(lcs63);
}

// ------------------------- K4b: sequential chunk scan -------------------------
__global__ __launch_bounds__(256) void k_scan() {
    extern __shared__ float sm[];
    float* GMs = sm;
    float* CBs = sm + 4096;
    float* xcs = sm + 8192;
    float* hs  = sm + 10240;
    float* wls = sm + 12352;
    int tid = threadIdx.x;
    int pt = blockIdx.x, h = blockIdx.y, b = blockIdx.z;
    int p0 = pt * 32;
    int bh = b * NH + h;
    for (int e = tid; e < 2112; e += 256) hs[e] = 0.f;
    int lgrp = tid >> 4;
    int pp = (tid & 15) * 2;
    int lb = lgrp * 4;

    for (int c = 0; c < NC; c++) {
        int bhc = bh * NC + c;
        int rbase = b * SEQ + c * CHK;
        __syncthreads();
        const float* gmp = g_GM + (size_t)bhc * 4096;
        #pragma unroll
        for (int i = 0; i < 4; i++) {
            int f4 = (tid + 256 * i) * 4;
            *(float4*)&GMs[f4] = *(const float4*)&gmp[f4];
            int l = f4 >> 6, n = f4 & 63;
            float4 cv = *(const float4*)(g_proj + (size_t)(rbase + l) * PROJ + OFF_C + h * NS + n);
            float sc = g_lcse[bhc * 64 + l];
            cv.x *= sc; cv.y *= sc; cv.z *= sc; cv.w *= sc;
            *(float4*)&CBs[f4] = cv;
        }
        {
            int lr = tid >> 5, p = tid & 31;
            #pragma unroll
            for (int k = 0; k < 8; k++) {
                int l = lr * 8 + k;
                xcs[l * 32 + p] = g_x[(size_t)(rbase + l) * DI + h * HD + p0 + p];
            }
        }
        if (tid < 64) wls[tid] = g_wl[bhc * 64 + tid];
        float decay = g_decay[bhc];
        __syncthreads();
        float a[4][2];
        #pragma unroll
        for (int li = 0; li < 4; li++) { a[li][0] = 0.f; a[li][1] = 0.f; }
        #pragma unroll 8
        for (int i = 0; i < 64; i++) {
            float xa = xcs[i * 32 + pp], xb = xcs[i * 32 + pp + 1];
            #pragma unroll
            for (int li = 0; li < 4; li++) {
                float g = GMs[(lb + li) * 64 + i];
                a[li][0] += g * xa; a[li][1] += g * xb;
            }
        }
        #pragma unroll 8
        for (int n = 0; n < 64; n++) {
            float ha = hs[n * 33 + pp], hb = hs[n * 33 + pp + 1];
            #pragma unroll
            for (int li = 0; li < 4; li++) {
                float ce = CBs[(lb + li) * 64 + n];
                a[li][0] += ce * ha; a[li][1] += ce * hb;
            }
        }
        #pragma unroll
        for (int li = 0; li < 4; li++) {
            float* yo = g_y + (size_t)(rbase + lb + li) * DI + h * HD + p0 + pp;
            yo[0] = a[li][0]; yo[1] = a[li][1];
        }
        __syncthreads();
        for (int e = tid; e < 2048; e += 256) { int l = e >> 5; xcs[e] *= wls[l]; }
        #pragma unroll
        for (int i = 0; i < 4; i++) {
            int f4 = (tid + 256 * i) * 4;
            int l = f4 >> 6, n = f4 & 63;
            *(float4*)&CBs[f4] =
                *(const float4*)(g_proj + (size_t)(rbase + l) * PROJ + OFF_B + h * NS + n);
        }
        __syncthreads();
        int nb = lgrp * 4;
        float f[4][2];
        #pragma unroll
        for (int ni = 0; ni < 4; ni++) {
            f[ni][0] = decay * hs[(nb + ni) * 33 + pp];
            f[ni][1] = decay * hs[(nb + ni) * 33 + pp + 1];
        }
        #pragma unroll 8
        for (int l = 0; l < 64; l++) {
            float xa = xcs[l * 32 + pp], xb = xcs[l * 32 + pp + 1];
            float4 bv = *(float4*)&CBs[l * 64 + nb];
            f[0][0] += bv.x * xa; f[0][1] += bv.x * xb;
            f[1][0] += bv.y * xa; f[1][1] += bv.y * xb;
            f[2][0] += bv.z * xa; f[2][1] += bv.z * xb;
            f[3][0] += bv.w * xa; f[3][1] += bv.w * xb;
        }
        #pragma unroll
        for (int ni = 0; ni < 4; ni++) {
            hs[(nb + ni) * 33 + pp] = f[ni][0];
            hs[(nb + ni) * 33 + pp + 1] = f[ni][1];
        }
    }
}

// ------------------------- K5: gate + RMSNorm (tf32-rounded output) -------------------------
__global__ __launch_bounds__(256) void k_gate(const float* __restrict__ Dp,
                                              const float* __restrict__ wno) {
    int row = blockIdx.x, tid = threadIdx.x;
    __shared__ float red[8];
    const float* yr = g_y + (size_t)row * DI;
    const float* xr = g_x + (size_t)row * DI;
    const float* zr = g_proj + (size_t)row * PROJ + OFF_Z;
    float vals[8];
    float ss = 0.f;
    #pragma unroll
    for (int k = 0; k < 8; k++) {
        int cidx = tid + 256 * k;
        int hh = cidx >> 8;
        float y = yr[cidx] + xr[cidx] * Dp[hh];
        float z = zr[cidx];
        float v = y * (z / (1.f + expf(-z)));
        vals[k] = v; ss += v * v;
    }
    ss = blk_reduce_sum(ss, red);
    float sc = rsqrtf(ss * (1.0f / DI) + EPSV);
    float* outp = g_yn + (size_t)row * DI;
    #pragma unroll
    for (int k = 0; k < 8; k++) {
        int cidx = tid + 256 * k;
        outp[cidx] = f2tf_f(vals[k] * sc * wno[cidx]);
    }
}

// ------------------------- launch -------------------------
extern "C" void kernel_launch(void* const* d_in, const int* in_sizes, int n_in,
                              void* d_out, int out_size) {
    const float* hidden = (const float*)d_in[0];
    const float* w_norm_in = (const float*)d_in[1];
    const float* w_in_proj = (const float*)d_in[2];
    const float* conv_w = (const float*)d_in[3];
    const float* conv_b = (const float*)d_in[4];
    const float* w_dt = (const float*)d_in[5];
    const float* b_dt = (const float*)d_in[6];
    const float* A_log = (const float*)d_in[7];
    const float* Dp = (const float*)d_in[8];
    const float* w_norm_out = (const float*)d_in[9];
    const float* w_out_proj = (const float*)d_in[10];
    float* out = (float*)d_out;

    float *p_normed, *p_proj, *p_yn, *p_w1t, *p_w2t;
    cudaGetSymbolAddress((void**)&p_normed, g_normed);
    cudaGetSymbolAddress((void**)&p_proj, g_proj);
    cudaGetSymbolAddress((void**)&p_yn, g_yn);
    cudaGetSymbolAddress((void**)&p_w1t, g_w1t);
    cudaGetSymbolAddress((void**)&p_w2t, g_w2t);

    cudaFuncSetAttribute(k_scan, cudaFuncAttributeMaxDynamicSharedMemorySize, 50176);
    cudaFuncSetAttribute(gemm_tc, cudaFuncAttributeMaxDynamicSharedMemorySize, 60416);

    int n4_1 = DM * PROJ / 4, n4_2 = DI * DM / 4;
    k_cvt<<<(n4_1 + 255) / 256, 256>>>(w_in_proj, p_w1t, n4_1);
    k_cvt<<<(n4_2 + 255) / 256, 256>>>(w_out_proj, p_w2t, n4_2);
    k_rms_in<<<ROWS, 256>>>(hidden, w_norm_in);
    gemm_tc<<<dim3((PROJ + 127) / 128, ROWS / 256), 256, 58368>>>(
        p_normed, p_w1t, nullptr, p_proj, ROWS, PROJ, DM, 0);
    k_conv<<<dim3(DI / 256, ROWS), 256>>>(conv_w, conv_b);
    k_dt<<<ROWS / 16, 256>>>(w_dt, b_dt);
    k_chunkprep<<<dim3(NC, NH, 2), 256>>>(A_log);
    k_scan<<<dim3(8, NH, 2), 256, 49664>>>();
    k_gate<<<ROWS, 256>>>(Dp, w_norm_out);
    gemm_tc<<<dim3(DM / 128, ROWS / 256), 256, 58368>>>(
        p_yn, p_w2t, hidden, out, ROWS, DM, DI, 1);
}

// round 6
// speedup vs baseline: 2.6357x; 1.2593x over previous
#include <cuda_runtime.h>
#include <cstdint>
#include <math.h>

#define ROWS   8192
#define SEQ    4096
#define DM     1024
#define DI     2048
#define NH     8
#define HD     256
#define NS     64
#define CHK    64
#define NC     64
#define PROJ   5128
#define PROJP  5376
#define OFF_Z  0
#define OFF_X  2048
#define OFF_B  4096
#define OFF_C  4608
#define OFF_DT 5120
#define EPSV   1.1920929e-7f

// ------------------------- scratch (device globals) -------------------------
__device__ float g_normed[ROWS * DM];              // tf32-rounded
__device__ float g_proj[(size_t)ROWS * PROJ];
__device__ float g_x[ROWS * DI];
__device__ float g_dt[ROWS * NH];
__device__ float g_GM[1024 * 4096];
__device__ float g_lcse[1024 * 64];
__device__ float g_wl[1024 * 64];
__device__ float g_decay[1024];
__device__ float g_y[ROWS * DI];
__device__ float g_yn[ROWS * DI];                  // tf32-rounded
__device__ float g_w1tt[(size_t)PROJP * DM];       // w_in_proj^T, tf32, padded
__device__ float g_w2tt[(size_t)DM * DI];          // w_out_proj^T, tf32

// ------------------------- helpers -------------------------
__device__ __forceinline__ float blk_reduce_sum(float v, float* red) {
    int tid = threadIdx.x;
    #pragma unroll
    for (int o = 16; o > 0; o >>= 1) v += __shfl_xor_sync(0xffffffffu, v, o);
    if ((tid & 31) == 0) red[tid >> 5] = v;
    __syncthreads();
    if (tid < 8) {
        float t = red[tid];
        #pragma unroll
        for (int o = 4; o > 0; o >>= 1) t += __shfl_xor_sync(0xffu, t, o);
        if (tid == 0) red[0] = t;
    }
    __syncthreads();
    return red[0];
}

__device__ __forceinline__ float f2tf_f(float f) {
    uint32_t o;
    asm("cvt.rna.tf32.f32 %0, %1;" : "=r"(o) : "f"(f));
    return __uint_as_float(o);
}

__device__ __forceinline__ uint32_t s2u(const void* p) {
    uint32_t a;
    asm("{ .reg .u64 t; cvta.to.shared.u64 t, %1; cvt.u32.u64 %0, t; }"
        : "=r"(a) : "l"(p));
    return a;
}

__device__ __forceinline__ void cp16s(uint32_t d, const void* s) {
    asm volatile("cp.async.cg.shared.global [%0], [%1], 16;\n" :: "r"(d), "l"(s));
}
__device__ __forceinline__ void cp_commit() {
    asm volatile("cp.async.commit_group;\n" ::);
}
template <int N>
__device__ __forceinline__ void cp_wait() {
    asm volatile("cp.async.wait_group %0;\n" :: "n"(N));
}

__device__ __forceinline__ void mma8(float* c, const uint32_t* a, const uint32_t* b) {
    asm volatile(
        "mma.sync.aligned.m16n8k8.row.col.f32.tf32.tf32.f32 "
        "{%0,%1,%2,%3},{%4,%5,%6,%7},{%8,%9},{%0,%1,%2,%3};\n"
        : "+f"(c[0]), "+f"(c[1]), "+f"(c[2]), "+f"(c[3])
        : "r"(a[0]), "r"(a[1]), "r"(a[2]), "r"(a[3]), "r"(b[0]), "r"(b[1]));
}

// ------------------------- K0: transpose + tf32 round weights -------------------------
__global__ __launch_bounds__(256) void k_tr(const float* __restrict__ in,
                                            float* __restrict__ out,
                                            int Kd, int Nin) {
    __shared__ float t[32][33];
    int k0 = blockIdx.x * 32, n0 = blockIdx.y * 32;
    int tx = threadIdx.x & 31, ty = threadIdx.x >> 5;
    #pragma unroll
    for (int i = ty; i < 32; i += 8) {
        int n = n0 + tx;
        float v = (n < Nin) ? in[(size_t)(k0 + i) * Nin + n] : 0.f;
        t[i][tx] = f2tf_f(v);
    }
    __syncthreads();
    #pragma unroll
    for (int i = ty; i < 32; i += 8)
        out[(size_t)(n0 + i) * Kd + k0 + tx] = t[tx][i];
}

// ------------------------- K1: input RMSNorm (tf32-rounded output) -------------------------
__global__ __launch_bounds__(256) void k_rms_in(const float* __restrict__ hidden,
                                                const float* __restrict__ w) {
    int row = blockIdx.x, tid = threadIdx.x;
    __shared__ float red[8];
    float4 v = ((const float4*)(hidden + (size_t)row * DM))[tid];
    float ss = v.x * v.x + v.y * v.y + v.z * v.z + v.w * v.w;
    ss = blk_reduce_sum(ss, red);
    float sc = rsqrtf(ss * (1.0f / DM) + EPSV);
    float4 wv = ((const float4*)w)[tid];
    float4 o;
    o.x = f2tf_f(v.x * sc * wv.x); o.y = f2tf_f(v.y * sc * wv.y);
    o.z = f2tf_f(v.z * sc * wv.z); o.w = f2tf_f(v.w * sc * wv.w);
    ((float4*)(g_normed + (size_t)row * DM))[tid] = o;
}

// ------------------------- TF32 mma.sync GEMM, LDS.64 fragments -------------------------
// C[M,N] = A[M,K] @ BT[N,K]^T (+R). BM=256, BN=128, Kstage=32, 3 stages,
// 256 thr (8 warps, 64x64 tiles). k remapped so frag pairs are smem-adjacent.
#define ASTR 40
#define A_FLOATS (256 * ASTR)
#define B_FLOATS (128 * ASTR)
#define STG_FLOATS (A_FLOATS + B_FLOATS)
#define NSTG 3
#define GSMEM (NSTG * STG_FLOATS * 4)

__device__ __forceinline__ void fill_stage(const float* __restrict__ A,
                                           const float* __restrict__ BT,
                                           float* __restrict__ sm, int s,
                                           int bm, int bn, int kt, int K, int tid) {
    float* As = sm + s * STG_FLOATS;
    float* Bs = As + A_FLOATS;
    uint32_t ab = s2u(As), bb = s2u(Bs);
    const float* Ap = A + (size_t)bm * K + kt * 32;
    #pragma unroll
    for (int j = 0; j < 8; j++) {
        int i = tid + 256 * j;
        int row = i >> 3, c = i & 7;
        cp16s(ab + (row * ASTR + c * 4) * 4, Ap + (size_t)row * K + c * 4);
    }
    const float* Bp = BT + (size_t)bn * K + kt * 32;
    #pragma unroll
    for (int j = 0; j < 4; j++) {
        int i = tid + 256 * j;
        int row = i >> 3, c = i & 7;
        cp16s(bb + (row * ASTR + c * 4) * 4, Bp + (size_t)row * K + c * 4);
    }
}

__global__ __launch_bounds__(256) void gemm_tc(const float* __restrict__ A,
                                               const float* __restrict__ BT,
                                               const float* __restrict__ R,
                                               float* __restrict__ C,
                                               int M, int N, int K, int addR) {
    extern __shared__ float smd[];
    int tid = threadIdx.x, lane = tid & 31, warp = tid >> 5;
    int bm = blockIdx.y * 256, bn = blockIdx.x * 128;
    int wm = (warp >> 1) * 64, wn = (warp & 1) * 64;
    int r = lane >> 2, cc = lane & 3;
    float acc[4][8][4];
    #pragma unroll
    for (int mi = 0; mi < 4; mi++)
        #pragma unroll
        for (int ni = 0; ni < 8; ni++)
            #pragma unroll
            for (int q = 0; q < 4; q++) acc[mi][ni][q] = 0.f;

    int nk = K >> 5;
    #pragma unroll
    for (int s = 0; s < NSTG; s++) {
        fill_stage(A, BT, smd, s, bm, bn, s, K, tid);
        cp_commit();
    }

    for (int kt = 0; kt < nk; kt++) {
        int s = kt % NSTG;
        cp_wait<NSTG - 1>();
        __syncthreads();
        const float* As = smd + s * STG_FLOATS;
        const float* Bs = As + A_FLOATS;
        const float* arow = As + (wm + r) * ASTR + 2 * cc;
        const float* brow = Bs + (wn + r) * ASTR + 2 * cc;
        #pragma unroll
        for (int k8 = 0; k8 < 32; k8 += 8) {
            uint32_t af[4][4];
            #pragma unroll
            for (int mi = 0; mi < 4; mi++) {
                float2 v0 = *(const float2*)(arow + mi * 16 * ASTR + k8);
                float2 v1 = *(const float2*)(arow + (mi * 16 + 8) * ASTR + k8);
                af[mi][0] = __float_as_uint(v0.x);
                af[mi][1] = __float_as_uint(v1.x);
                af[mi][2] = __float_as_uint(v0.y);
                af[mi][3] = __float_as_uint(v1.y);
            }
            uint32_t bf[8][2];
            #pragma unroll
            for (int ni = 0; ni < 8; ni++) {
                float2 w = *(const float2*)(brow + ni * 8 * ASTR + k8);
                bf[ni][0] = __float_as_uint(w.x);
                bf[ni][1] = __float_as_uint(w.y);
            }
            #pragma unroll
            for (int mi = 0; mi < 4; mi++)
                #pragma unroll
                for (int ni = 0; ni < 8; ni++)
                    mma8(acc[mi][ni], af[mi], bf[ni]);
        }
        __syncthreads();
        if (kt + NSTG < nk) {
            fill_stage(A, BT, smd, s, bm, bn, kt + NSTG, K, tid);
            cp_commit();
        } else {
            cp_commit();
        }
    }

    #pragma unroll
    for (int mi = 0; mi < 4; mi++) {
        int row = bm + wm + mi * 16 + r;
        #pragma unroll
        for (int ni = 0; ni < 8; ni++) {
            int col = bn + wn + ni * 8 + 2 * cc;
            if (col < N) {
                size_t o0 = (size_t)row * N + col;
                size_t o1 = (size_t)(row + 8) * N + col;
                float2 v0 = make_float2(acc[mi][ni][0], acc[mi][ni][1]);
                float2 v1 = make_float2(acc[mi][ni][2], acc[mi][ni][3]);
                if (addR) {
                    float2 r0 = *(const float2*)(R + o0);
                    float2 r1 = *(const float2*)(R + o1);
                    v0.x += r0.x; v0.y += r0.y;
                    v1.x += r1.x; v1.y += r1.y;
                }
                *(float2*)(C + o0) = v0;
                *(float2*)(C + o1) = v1;
            }
        }
    }
}

// ------------------------- K3: causal depthwise conv + SiLU -------------------------
__global__ __launch_bounds__(256) void k_conv(const float* __restrict__ cw,
                                              const float* __restrict__ cb) {
    int c = blockIdx.x * 256 + threadIdx.x;
    int row = blockIdx.y;
    int s = row & (SEQ - 1);
    float w0 = cw[c * 4 + 0], w1 = cw[c * 4 + 1], w2 = cw[c * 4 + 2], w3 = cw[c * 4 + 3];
    const float* xp = g_proj + (size_t)row * PROJ + OFF_X + c;
    float acc = cb[c] + w3 * xp[0];
    if (s >= 1) acc += w2 * xp[-(int)PROJ];
    if (s >= 2) acc += w1 * xp[-2 * (int)PROJ];
    if (s >= 3) acc += w0 * xp[-3 * (int)PROJ];
    g_x[(size_t)row * DI + c] = acc / (1.f + expf(-acc));
}

// ------------------------- K3b: dt -------------------------
__global__ __launch_bounds__(256) void k_dt(const float* __restrict__ wdt,
                                            const float* __restrict__ bdt) {
    int tid = threadIdx.x;
    int h = tid >> 5, lane = tid & 31;
    int d0 = h * HD + lane * 8;
    float w[8][8], bb[8];
    #pragma unroll
    for (int j = 0; j < 8; j++)
        #pragma unroll
        for (int q = 0; q < 8; q++) w[j][q] = wdt[j * DI + d0 + q];
    #pragma unroll
    for (int q = 0; q < 8; q++) bb[q] = bdt[d0 + q];

    int row0 = blockIdx.x * 16;
    for (int rr = 0; rr < 16; rr++) {
        int row = row0 + rr;
        const float* pr = g_proj + (size_t)row * PROJ + OFF_DT;
        float dtr[8];
        #pragma unroll
        for (int j = 0; j < 8; j++) dtr[j] = pr[j];
        float acc = 0.f;
        #pragma unroll
        for (int q = 0; q < 8; q++) {
            float v = bb[q];
            #pragma unroll
            for (int j = 0; j < 8; j++) v += dtr[j] * w[j][q];
            acc += (v > 20.f) ? v : log1pf(expf(v));
        }
        #pragma unroll
        for (int o = 16; o > 0; o >>= 1) acc += __shfl_xor_sync(0xffffffffu, acc, o);
        if (lane == 0) g_dt[row * NH + h] = acc * (1.0f / HD);
    }
}

// ------------------------- K4a: chunk prep -------------------------
__global__ __launch_bounds__(256) void k_chunkprep(const float* __restrict__ A_log) {
    int c = blockIdx.x, h = blockIdx.y, b = blockIdx.z;
    int bhc = (b * NH + h) * NC + c;
    int rbase = b * SEQ + c * CHK;
    __shared__ float Bc[64 * 68];
    __shared__ float Cc[64 * 68];
    __shared__ float lcs[64];
    __shared__ float sdt[64];
    int tid = threadIdx.x;
    float A = -expf(A_log[h]);
    if (tid < 64) sdt[tid] = g_dt[(rbase + tid) * NH + h] * A;
    #pragma unroll
    for (int i = 0; i < 4; i++) {
        int f = (tid + 256 * i) * 4;
        int l = f >> 6, n = f & 63;
        const float* pr = g_proj + (size_t)(rbase + l) * PROJ;
        float4 bv = *(const float4*)(pr + OFF_B + h * NS + n);
        float4 cv = *(const float4*)(pr + OFF_C + h * NS + n);
        Bc[l * 68 + n + 0] = bv.x; Bc[l * 68 + n + 1] = bv.y;
        Bc[l * 68 + n + 2] = bv.z; Bc[l * 68 + n + 3] = bv.w;
        Cc[l * 68 + n + 0] = cv.x; Cc[l * 68 + n + 1] = cv.y;
        Cc[l * 68 + n + 2] = cv.z; Cc[l * 68 + n + 3] = cv.w;
    }
    __syncthreads();
    if (tid == 0) {
        float run = 0.f;
        for (int l = 0; l < 64; l++) { run += sdt[l]; lcs[l] = run; }
    }
    __syncthreads();
    float lcs63 = lcs[63];
    int l = tid >> 2, i0 = (tid & 3) * 16;
    float* outp = g_GM + (size_t)bhc * 4096;
    float myl = lcs[l];
    for (int q = 0; q < 16; q++) {
        int i = i0 + q;
        float g = 0.f;
        #pragma unroll
        for (int n = 0; n < 64; n++) g += Cc[l * 68 + n] * Bc[i * 68 + n];
        float m = (i <= l) ? expf(myl - lcs[i]) : 0.f;
        outp[l * 64 + i] = m * g;
    }
    if (tid < 64) {
        g_lcse[bhc * 64 + tid] = expf(lcs[tid]);
        g_wl[bhc * 64 + tid] = expf(lcs63 - lcs[tid]);
    }
    if (tid == 0) g_decay[bhc] = expf(lcs63);
}

// ------------------------- K4b: sequential chunk scan -------------------------
__global__ __launch_bounds__(256) void k_scan() {
    extern __shared__ float sm[];
    float* GMs = sm;
    float* CBs = sm + 4096;
    float* xcs = sm + 8192;
    float* hs  = sm + 10240;
    float* wls = sm + 12352;
    int tid = threadIdx.x;
    int pt = blockIdx.x, h = blockIdx.y, b = blockIdx.z;
    int p0 = pt * 32;
    int bh = b * NH + h;
    for (int e = tid; e < 2112; e += 256) hs[e] = 0.f;
    int lgrp = tid >> 4;
    int pp = (tid & 15) * 2;
    int lb = lgrp * 4;

    for (int c = 0; c < NC; c++) {
        int bhc = bh * NC + c;
        int rbase = b * SEQ + c * CHK;
        __syncthreads();
        const float* gmp = g_GM + (size_t)bhc * 4096;
        #pragma unroll
        for (int i = 0; i < 4; i++) {
            int f4 = (tid + 256 * i) * 4;
            *(float4*)&GMs[f4] = *(const float4*)&gmp[f4];
            int l = f4 >> 6, n = f4 & 63;
            float4 cv = *(const float4*)(g_proj + (size_t)(rbase + l) * PROJ + OFF_C + h * NS + n);
            float sc = g_lcse[bhc * 64 + l];
            cv.x *= sc; cv.y *= sc; cv.z *= sc; cv.w *= sc;
            *(float4*)&CBs[f4] = cv;
        }
        {
            int lr = tid >> 5, p = tid & 31;
            #pragma unroll
            for (int k = 0; k < 8; k++) {
                int l = lr * 8 + k;
                xcs[l * 32 + p] = g_x[(size_t)(rbase + l) * DI + h * HD + p0 + p];
            }
        }
        if (tid < 64) wls[tid] = g_wl[bhc * 64 + tid];
        float decay = g_decay[bhc];
        __syncthreads();
        float a[4][2];
        #pragma unroll
        for (int li = 0; li < 4; li++) { a[li][0] = 0.f; a[li][1] = 0.f; }
        #pragma unroll 8
        for (int i = 0; i < 64; i++) {
            float xa = xcs[i * 32 + pp], xb = xcs[i * 32 + pp + 1];
            #pragma unroll
            for (int li = 0; li < 4; li++) {
                float g = GMs[(lb + li) * 64 + i];
                a[li][0] += g * xa; a[li][1] += g * xb;
            }
        }
        #pragma unroll 8
        for (int n = 0; n < 64; n++) {
            float ha = hs[n * 33 + pp], hb = hs[n * 33 + pp + 1];
            #pragma unroll
            for (int li = 0; li < 4; li++) {
                float ce = CBs[(lb + li) * 64 + n];
                a[li][0] += ce * ha; a[li][1] += ce * hb;
            }
        }
        #pragma unroll
        for (int li = 0; li < 4; li++) {
            float* yo = g_y + (size_t)(rbase + lb + li) * DI + h * HD + p0 + pp;
            yo[0] = a[li][0]; yo[1] = a[li][1];
        }
        __syncthreads();
        for (int e = tid; e < 2048; e += 256) { int l = e >> 5; xcs[e] *= wls[l]; }
        #pragma unroll
        for (int i = 0; i < 4; i++) {
            int f4 = (tid + 256 * i) * 4;
            int l = f4 >> 6, n = f4 & 63;
            *(float4*)&CBs[f4] =
                *(const float4*)(g_proj + (size_t)(rbase + l) * PROJ + OFF_B + h * NS + n);
        }
        __syncthreads();
        int nb = lgrp * 4;
        float f[4][2];
        #pragma unroll
        for (int ni = 0; ni < 4; ni++) {
            f[ni][0] = decay * hs[(nb + ni) * 33 + pp];
            f[ni][1] = decay * hs[(nb + ni) * 33 + pp + 1];
        }
        #pragma unroll 8
        for (int l = 0; l < 64; l++) {
            float xa = xcs[l * 32 + pp], xb = xcs[l * 32 + pp + 1];
            float4 bv = *(float4*)&CBs[l * 64 + nb];
            f[0][0] += bv.x * xa; f[0][1] += bv.x * xb;
            f[1][0] += bv.y * xa; f[1][1] += bv.y * xb;
            f[2][0] += bv.z * xa; f[2][1] += bv.z * xb;
            f[3][0] += bv.w * xa; f[3][1] += bv.w * xb;
        }
        #pragma unroll
        for (int ni = 0; ni < 4; ni++) {
            hs[(nb + ni) * 33 + pp] = f[ni][0];
            hs[(nb + ni) * 33 + pp + 1] = f[ni][1];
        }
    }
}

// ------------------------- K5: gate + RMSNorm (tf32-rounded output) -------------------------
__global__ __launch_bounds__(256) void k_gate(const float* __restrict__ Dp,
                                              const float* __restrict__ wno) {
    int row = blockIdx.x, tid = threadIdx.x;
    __shared__ float red[8];
    const float* yr = g_y + (size_t)row * DI;
    const float* xr = g_x + (size_t)row * DI;
    const float* zr = g_proj + (size_t)row * PROJ + OFF_Z;
    float vals[8];
    float ss = 0.f;
    #pragma unroll
    for (int k = 0; k < 8; k++) {
        int cidx = tid + 256 * k;
        int hh = cidx >> 8;
        float y = yr[cidx] + xr[cidx] * Dp[hh];
        float z = zr[cidx];
        float v = y * (z / (1.f + expf(-z)));
        vals[k] = v; ss += v * v;
    }
    ss = blk_reduce_sum(ss, red);
    float sc = rsqrtf(ss * (1.0f / DI) + EPSV);
    float* outp = g_yn + (size_t)row * DI;
    #pragma unroll
    for (int k = 0; k < 8; k++) {
        int cidx = tid + 256 * k;
        outp[cidx] = f2tf_f(vals[k] * sc * wno[cidx]);
    }
}

// ------------------------- launch -------------------------
extern "C" void kernel_launch(void* const* d_in, const int* in_sizes, int n_in,
                              void* d_out, int out_size) {
    const float* hidden = (const float*)d_in[0];
    const float* w_norm_in = (const float*)d_in[1];
    const float* w_in_proj = (const float*)d_in[2];
    const float* conv_w = (const float*)d_in[3];
    const float* conv_b = (const float*)d_in[4];
    const float* w_dt = (const float*)d_in[5];
    const float* b_dt = (const float*)d_in[6];
    const float* A_log = (const float*)d_in[7];
    const float* Dp = (const float*)d_in[8];
    const float* w_norm_out = (const float*)d_in[9];
    const float* w_out_proj = (const float*)d_in[10];
    float* out = (float*)d_out;

    float *p_normed, *p_proj, *p_yn, *p_w1tt, *p_w2tt;
    cudaGetSymbolAddress((void**)&p_normed, g_normed);
    cudaGetSymbolAddress((void**)&p_proj, g_proj);
    cudaGetSymbolAddress((void**)&p_yn, g_yn);
    cudaGetSymbolAddress((void**)&p_w1tt, g_w1tt);
    cudaGetSymbolAddress((void**)&p_w2tt, g_w2tt);

    cudaFuncSetAttribute(k_scan, cudaFuncAttributeMaxDynamicSharedMemorySize, 50176);
    cudaFuncSetAttribute(gemm_tc, cudaFuncAttributeMaxDynamicSharedMemorySize, GSMEM);

    k_tr<<<dim3(DM / 32, PROJP / 32), 256>>>(w_in_proj, p_w1tt, DM, PROJ);
    k_tr<<<dim3(DI / 32, DM / 32), 256>>>(w_out_proj, p_w2tt, DI, DM);
    k_rms_in<<<ROWS, 256>>>(hidden, w_norm_in);
    gemm_tc<<<dim3(PROJP / 128, ROWS / 256), 256, GSMEM>>>(
        p_normed, p_w1tt, nullptr, p_proj, ROWS, PROJ, DM, 0);
    k_conv<<<dim3(DI / 256, ROWS), 256>>>(conv_w, conv_b);
    k_dt<<<ROWS / 16, 256>>>(w_dt, b_dt);
    k_chunkprep<<<dim3(NC, NH, 2), 256>>>(A_log);
    k_scan<<<dim3(8, NH, 2), 256, 49664>>>();
    k_gate<<<ROWS, 256>>>(Dp, w_norm_out);
    gemm_tc<<<dim3(DM / 128, ROWS / 256), 256, GSMEM>>>(
        p_yn, p_w2tt, hidden, out, ROWS, DM, DI, 1);
}

// round 7
// speedup vs baseline: 3.0661x; 1.1633x over previous
#include <cuda_runtime.h>
#include <cstdint>
#include <math.h>

#define ROWS   8192
#define SEQ    4096
#define DM     1024
#define DI     2048
#define NH     8
#define HD     256
#define NS     64
#define CHK    64
#define NC     64
#define PROJ   5128
#define PROJP  5376
#define OFF_Z  0
#define OFF_X  2048
#define OFF_B  4096
#define OFF_C  4608
#define OFF_DT 5120
#define EPSV   1.1920929e-7f

// ------------------------- scratch (device globals) -------------------------
__device__ float g_normed[ROWS * DM];              // tf32-rounded
__device__ float g_proj[(size_t)ROWS * PROJ];
__device__ float g_x[ROWS * DI];
__device__ float g_dt[ROWS * NH];
__device__ float g_GM[1024 * 4096];
__device__ float g_lcse[1024 * 64];
__device__ float g_wl[1024 * 64];
__device__ float g_decay[1024];
__device__ float g_y[ROWS * DI];
__device__ float g_yn[ROWS * DI];                  // tf32-rounded
__device__ float g_w1tt[(size_t)PROJP * DM];       // w_in_proj^T, tf32, padded
__device__ float g_w2tt[(size_t)DM * DI];          // w_out_proj^T, tf32

// ------------------------- helpers -------------------------
__device__ __forceinline__ float blk_reduce_sum(float v, float* red) {
    int tid = threadIdx.x;
    #pragma unroll
    for (int o = 16; o > 0; o >>= 1) v += __shfl_xor_sync(0xffffffffu, v, o);
    if ((tid & 31) == 0) red[tid >> 5] = v;
    __syncthreads();
    if (tid < 8) {
        float t = red[tid];
        #pragma unroll
        for (int o = 4; o > 0; o >>= 1) t += __shfl_xor_sync(0xffu, t, o);
        if (tid == 0) red[0] = t;
    }
    __syncthreads();
    return red[0];
}

__device__ __forceinline__ float f2tf_f(float f) {
    uint32_t o;
    asm("cvt.rna.tf32.f32 %0, %1;" : "=r"(o) : "f"(f));
    return __uint_as_float(o);
}

__device__ __forceinline__ uint32_t s2u(const void* p) {
    uint32_t a;
    asm("{ .reg .u64 t; cvta.to.shared.u64 t, %1; cvt.u32.u64 %0, t; }"
        : "=r"(a) : "l"(p));
    return a;
}

__device__ __forceinline__ void cp16s(uint32_t d, const void* s) {
    asm volatile("cp.async.cg.shared.global [%0], [%1], 16;\n" :: "r"(d), "l"(s));
}
__device__ __forceinline__ void cp_commit() {
    asm volatile("cp.async.commit_group;\n" ::);
}
template <int N>
__device__ __forceinline__ void cp_wait() {
    asm volatile("cp.async.wait_group %0;\n" :: "n"(N));
}

__device__ __forceinline__ void mma8(float* c, const uint32_t* a, const uint32_t* b) {
    asm volatile(
        "mma.sync.aligned.m16n8k8.row.col.f32.tf32.tf32.f32 "
        "{%0,%1,%2,%3},{%4,%5,%6,%7},{%8,%9},{%0,%1,%2,%3};\n"
        : "+f"(c[0]), "+f"(c[1]), "+f"(c[2]), "+f"(c[3])
        : "r"(a[0]), "r"(a[1]), "r"(a[2]), "r"(a[3]), "r"(b[0]), "r"(b[1]));
}

// ------------------------- K0: transpose + tf32 round weights -------------------------
__global__ __launch_bounds__(256) void k_tr(const float* __restrict__ in,
                                            float* __restrict__ out,
                                            int Kd, int Nin) {
    __shared__ float t[32][33];
    int k0 = blockIdx.x * 32, n0 = blockIdx.y * 32;
    int tx = threadIdx.x & 31, ty = threadIdx.x >> 5;
    #pragma unroll
    for (int i = ty; i < 32; i += 8) {
        int n = n0 + tx;
        float v = (n < Nin) ? in[(size_t)(k0 + i) * Nin + n] : 0.f;
        t[i][tx] = f2tf_f(v);
    }
    __syncthreads();
    #pragma unroll
    for (int i = ty; i < 32; i += 8)
        out[(size_t)(n0 + i) * Kd + k0 + tx] = t[tx][i];
}

// ------------------------- K1: input RMSNorm (tf32-rounded output) -------------------------
__global__ __launch_bounds__(256) void k_rms_in(const float* __restrict__ hidden,
                                                const float* __restrict__ w) {
    int row = blockIdx.x, tid = threadIdx.x;
    __shared__ float red[8];
    float4 v = ((const float4*)(hidden + (size_t)row * DM))[tid];
    float ss = v.x * v.x + v.y * v.y + v.z * v.z + v.w * v.w;
    ss = blk_reduce_sum(ss, red);
    float sc = rsqrtf(ss * (1.0f / DM) + EPSV);
    float4 wv = ((const float4*)w)[tid];
    float4 o;
    o.x = f2tf_f(v.x * sc * wv.x); o.y = f2tf_f(v.y * sc * wv.y);
    o.z = f2tf_f(v.z * sc * wv.z); o.w = f2tf_f(v.w * sc * wv.w);
    ((float4*)(g_normed + (size_t)row * DM))[tid] = o;
}

// ------------------------- TF32 mma.sync GEMM, LDS.64 fragments -------------------------
#define ASTR 40
#define A_FLOATS (256 * ASTR)
#define B_FLOATS (128 * ASTR)
#define STG_FLOATS (A_FLOATS + B_FLOATS)
#define NSTG 3
#define GSMEM (NSTG * STG_FLOATS * 4)

__device__ __forceinline__ void fill_stage(const float* __restrict__ A,
                                           const float* __restrict__ BT,
                                           float* __restrict__ sm, int s,
                                           int bm, int bn, int kt, int K, int tid) {
    float* As = sm + s * STG_FLOATS;
    float* Bs = As + A_FLOATS;
    uint32_t ab = s2u(As), bb = s2u(Bs);
    const float* Ap = A + (size_t)bm * K + kt * 32;
    #pragma unroll
    for (int j = 0; j < 8; j++) {
        int i = tid + 256 * j;
        int row = i >> 3, c = i & 7;
        cp16s(ab + (row * ASTR + c * 4) * 4, Ap + (size_t)row * K + c * 4);
    }
    const float* Bp = BT + (size_t)bn * K + kt * 32;
    #pragma unroll
    for (int j = 0; j < 4; j++) {
        int i = tid + 256 * j;
        int row = i >> 3, c = i & 7;
        cp16s(bb + (row * ASTR + c * 4) * 4, Bp + (size_t)row * K + c * 4);
    }
}

__global__ __launch_bounds__(256) void gemm_tc(const float* __restrict__ A,
                                               const float* __restrict__ BT,
                                               const float* __restrict__ R,
                                               float* __restrict__ C,
                                               int M, int N, int K, int addR) {
    extern __shared__ float smd[];
    int tid = threadIdx.x, lane = tid & 31, warp = tid >> 5;
    int bm = blockIdx.y * 256, bn = blockIdx.x * 128;
    int wm = (warp >> 1) * 64, wn = (warp & 1) * 64;
    int r = lane >> 2, cc = lane & 3;
    float acc[4][8][4];
    #pragma unroll
    for (int mi = 0; mi < 4; mi++)
        #pragma unroll
        for (int ni = 0; ni < 8; ni++)
            #pragma unroll
            for (int q = 0; q < 4; q++) acc[mi][ni][q] = 0.f;

    int nk = K >> 5;
    // prologue: NSTG-1 stages
    #pragma unroll
    for (int s = 0; s < NSTG - 1; s++) {
        fill_stage(A, BT, smd, s, bm, bn, s, K, tid);
        cp_commit();
    }

    for (int kt = 0; kt < nk; kt++) {
        int s = kt % NSTG;
        cp_wait<NSTG - 2>();
        __syncthreads();
        // prefetch kt+2 into stage consumed at kt-1 (all warps past sync)
        if (kt + 2 < nk) fill_stage(A, BT, smd, (kt + 2) % NSTG, bm, bn, kt + 2, K, tid);
        cp_commit();

        const float* As = smd + s * STG_FLOATS;
        const float* Bs = As + A_FLOATS;
        const float* arow = As + (wm + r) * ASTR + 2 * cc;
        const float* brow = Bs + (wn + r) * ASTR + 2 * cc;
        #pragma unroll
        for (int k8 = 0; k8 < 32; k8 += 8) {
            uint32_t af[4][4];
            #pragma unroll
            for (int mi = 0; mi < 4; mi++) {
                float2 v0 = *(const float2*)(arow + mi * 16 * ASTR + k8);
                float2 v1 = *(const float2*)(arow + (mi * 16 + 8) * ASTR + k8);
                af[mi][0] = __float_as_uint(v0.x);
                af[mi][1] = __float_as_uint(v1.x);
                af[mi][2] = __float_as_uint(v0.y);
                af[mi][3] = __float_as_uint(v1.y);
            }
            uint32_t bf[8][2];
            #pragma unroll
            for (int ni = 0; ni < 8; ni++) {
                float2 w = *(const float2*)(brow + ni * 8 * ASTR + k8);
                bf[ni][0] = __float_as_uint(w.x);
                bf[ni][1] = __float_as_uint(w.y);
            }
            #pragma unroll
            for (int mi = 0; mi < 4; mi++)
                #pragma unroll
                for (int ni = 0; ni < 8; ni++)
                    mma8(acc[mi][ni], af[mi], bf[ni]);
        }
    }

    #pragma unroll
    for (int mi = 0; mi < 4; mi++) {
        int row = bm + wm + mi * 16 + r;
        #pragma unroll
        for (int ni = 0; ni < 8; ni++) {
            int col = bn + wn + ni * 8 + 2 * cc;
            if (col < N) {
                size_t o0 = (size_t)row * N + col;
                size_t o1 = (size_t)(row + 8) * N + col;
                float2 v0 = make_float2(acc[mi][ni][0], acc[mi][ni][1]);
                float2 v1 = make_float2(acc[mi][ni][2], acc[mi][ni][3]);
                if (addR) {
                    float2 r0 = *(const float2*)(R + o0);
                    float2 r1 = *(const float2*)(R + o1);
                    v0.x += r0.x; v0.y += r0.y;
                    v1.x += r1.x; v1.y += r1.y;
                }
                *(float2*)(C + o0) = v0;
                *(float2*)(C + o1) = v1;
            }
        }
    }
}

// ------------------------- K3: causal depthwise conv + SiLU (rolling window) -------------------------
__global__ __launch_bounds__(256) void k_conv(const float* __restrict__ cw,
                                              const float* __restrict__ cb) {
    int c = blockIdx.x * 256 + threadIdx.x;
    int row0 = blockIdx.y * 8;
    int s0 = row0 & (SEQ - 1);
    float w0 = cw[c * 4 + 0], w1 = cw[c * 4 + 1], w2 = cw[c * 4 + 2], w3 = cw[c * 4 + 3];
    const float* xp = g_proj + (size_t)row0 * PROJ + OFF_X + c;
    float x0 = (s0 >= 3) ? xp[-3 * (int)PROJ] : 0.f;
    float x1 = (s0 >= 2) ? xp[-2 * (int)PROJ] : 0.f;
    float x2 = (s0 >= 1) ? xp[-(int)PROJ] : 0.f;
    float bias = cb[c];
    #pragma unroll
    for (int k = 0; k < 8; k++) {
        float x3 = xp[(size_t)k * PROJ];
        float acc = bias + w0 * x0 + w1 * x1 + w2 * x2 + w3 * x3;
        g_x[(size_t)(row0 + k) * DI + c] = acc / (1.f + expf(-acc));
        x0 = x1; x1 = x2; x2 = x3;
    }
}

// ------------------------- K3b: dt -------------------------
__global__ __launch_bounds__(256) void k_dt(const float* __restrict__ wdt,
                                            const float* __restrict__ bdt) {
    int tid = threadIdx.x;
    int h = tid >> 5, lane = tid & 31;
    int d0 = h * HD + lane * 8;
    float w[8][8], bb[8];
    #pragma unroll
    for (int j = 0; j < 8; j++)
        #pragma unroll
        for (int q = 0; q < 8; q++) w[j][q] = wdt[j * DI + d0 + q];
    #pragma unroll
    for (int q = 0; q < 8; q++) bb[q] = bdt[d0 + q];

    int row0 = blockIdx.x * 16;
    for (int rr = 0; rr < 16; rr++) {
        int row = row0 + rr;
        const float* pr = g_proj + (size_t)row * PROJ + OFF_DT;
        float dtr[8];
        #pragma unroll
        for (int j = 0; j < 8; j++) dtr[j] = pr[j];
        float acc = 0.f;
        #pragma unroll
        for (int q = 0; q < 8; q++) {
            float v = bb[q];
            #pragma unroll
            for (int j = 0; j < 8; j++) v += dtr[j] * w[j][q];
            acc += (v > 20.f) ? v : log1pf(expf(v));
        }
        #pragma unroll
        for (int o = 16; o > 0; o >>= 1) acc += __shfl_xor_sync(0xffffffffu, acc, o);
        if (lane == 0) g_dt[row * NH + h] = acc * (1.0f / HD);
    }
}

// ------------------------- K4a: chunk prep -------------------------
__global__ __launch_bounds__(256) void k_chunkprep(const float* __restrict__ A_log) {
    int c = blockIdx.x, h = blockIdx.y, b = blockIdx.z;
    int bhc = (b * NH + h) * NC + c;
    int rbase = b * SEQ + c * CHK;
    __shared__ float Bc[64 * 68];
    __shared__ float Cc[64 * 68];
    __shared__ float lcs[64];
    __shared__ float sdt[64];
    int tid = threadIdx.x;
    float A = -expf(A_log[h]);
    if (tid < 64) sdt[tid] = g_dt[(rbase + tid) * NH + h] * A;
    #pragma unroll
    for (int i = 0; i < 4; i++) {
        int f = (tid + 256 * i) * 4;
        int l = f >> 6, n = f & 63;
        const float* pr = g_proj + (size_t)(rbase + l) * PROJ;
        float4 bv = *(const float4*)(pr + OFF_B + h * NS + n);
        float4 cv = *(const float4*)(pr + OFF_C + h * NS + n);
        Bc[l * 68 + n + 0] = bv.x; Bc[l * 68 + n + 1] = bv.y;
        Bc[l * 68 + n + 2] = bv.z; Bc[l * 68 + n + 3] = bv.w;
        Cc[l * 68 + n + 0] = cv.x; Cc[l * 68 + n + 1] = cv.y;
        Cc[l * 68 + n + 2] = cv.z; Cc[l * 68 + n + 3] = cv.w;
    }
    __syncthreads();
    if (tid == 0) {
        float run = 0.f;
        for (int l = 0; l < 64; l++) { run += sdt[l]; lcs[l] = run; }
    }
    __syncthreads();
    float lcs63 = lcs[63];
    int l = tid >> 2, i0 = (tid & 3) * 16;
    float* outp = g_GM + (size_t)bhc * 4096;
    float myl = lcs[l];
    for (int q = 0; q < 16; q++) {
        int i = i0 + q;
        float g = 0.f;
        #pragma unroll
        for (int n = 0; n < 64; n++) g += Cc[l * 68 + n] * Bc[i * 68 + n];
        float m = (i <= l) ? expf(myl - lcs[i]) : 0.f;
        outp[l * 64 + i] = m * g;
    }
    if (tid < 64) {
        g_lcse[bhc * 64 + tid] = expf(lcs[tid]);
        g_wl[bhc * 64 + tid] = expf(lcs63 - lcs[tid]);
    }
    if (tid == 0) g_decay[bhc] = expf(lcs63);
}

// ------------------------- K4b: mma-based sequential chunk scan -------------------------
// grid (8 p-tiles, NH, 2). Block: 256 thr (8 warps). Per chunk, three 64x32x64
// tf32 matmuls: y = GM@x + Ce@hT ; h = decay*h + Btw@x. h kept in registers.
#define SSTR 72
#define SC_GM   0
#define SC_CE   (64 * SSTR)
#define SC_BT   (2 * 64 * SSTR)
#define SC_XT   (3 * 64 * SSTR)
#define SC_HT   (3 * 64 * SSTR + 32 * SSTR)
#define SC_SMEM ((3 * 64 + 2 * 32) * SSTR * 4)

__device__ __forceinline__ void mm_tile(float* accA, float* accB,
                                        const float* Asm, const float* Bsm,
                                        int mt, int nt2, int r, int cc) {
    const float* ap = Asm + (mt * 16 + r) * SSTR + 2 * cc;
    const float* bp0 = Bsm + (nt2 * 8 + r) * SSTR + 2 * cc;
    const float* bp1 = bp0 + 8 * SSTR;
    #pragma unroll
    for (int k8 = 0; k8 < 64; k8 += 8) {
        float2 a0 = *(const float2*)(ap + k8);
        float2 a1 = *(const float2*)(ap + 8 * SSTR + k8);
        uint32_t af[4] = {__float_as_uint(a0.x), __float_as_uint(a1.x),
                          __float_as_uint(a0.y), __float_as_uint(a1.y)};
        float2 b0 = *(const float2*)(bp0 + k8);
        float2 b1 = *(const float2*)(bp1 + k8);
        uint32_t bf0[2] = {__float_as_uint(b0.x), __float_as_uint(b0.y)};
        uint32_t bf1[2] = {__float_as_uint(b1.x), __float_as_uint(b1.y)};
        mma8(accA, af, bf0);
        mma8(accB, af, bf1);
    }
}

__global__ __launch_bounds__(256) void k_scan() {
    extern __shared__ float sm[];
    float* GMs = sm + SC_GM;
    float* Ces = sm + SC_CE;
    float* Bts = sm + SC_BT;
    float* xTs = sm + SC_XT;
    float* hTs = sm + SC_HT;
    int tid = threadIdx.x, lane = tid & 31, w = tid >> 5;
    int pt = blockIdx.x, h = blockIdx.y, b = blockIdx.z;
    int p0 = pt * 32, bh = b * NH + h;
    int r = lane >> 2, cc = lane & 3;
    int mt = w & 3, nt2 = (w >> 2) * 2;

    for (int e = tid; e < 32 * SSTR; e += 256) hTs[e] = 0.f;
    float hA[4] = {0.f, 0.f, 0.f, 0.f};
    float hB[4] = {0.f, 0.f, 0.f, 0.f};

    for (int c = 0; c < NC; c++) {
        int bhc = bh * NC + c;
        int rbase = b * SEQ + c * CHK;
        __syncthreads();
        // ---- load phase ----
        const float* gmp = g_GM + (size_t)bhc * 4096;
        const float* lcp = g_lcse + bhc * 64;
        const float* wlp = g_wl + bhc * 64;
        #pragma unroll
        for (int i = 0; i < 4; i++) {
            int f4 = (tid + 256 * i) * 4;
            int l = f4 >> 6, n = f4 & 63;
            float4 gv = *(const float4*)&gmp[f4];
            gv.x = f2tf_f(gv.x); gv.y = f2tf_f(gv.y);
            gv.z = f2tf_f(gv.z); gv.w = f2tf_f(gv.w);
            *(float4*)&GMs[l * SSTR + n] = gv;
            const float* pr = g_proj + (size_t)(rbase + l) * PROJ;
            float lc = lcp[l];
            float4 cv = *(const float4*)(pr + OFF_C + h * NS + n);
            cv.x = f2tf_f(cv.x * lc); cv.y = f2tf_f(cv.y * lc);
            cv.z = f2tf_f(cv.z * lc); cv.w = f2tf_f(cv.w * lc);
            *(float4*)&Ces[l * SSTR + n] = cv;
            float wl = wlp[l];
            float4 bv = *(const float4*)(pr + OFF_B + h * NS + n);
            Bts[(n + 0) * SSTR + l] = f2tf_f(bv.x * wl);
            Bts[(n + 1) * SSTR + l] = f2tf_f(bv.y * wl);
            Bts[(n + 2) * SSTR + l] = f2tf_f(bv.z * wl);
            Bts[(n + 3) * SSTR + l] = f2tf_f(bv.w * wl);
        }
        #pragma unroll
        for (int i = 0; i < 2; i++) {
            int idx = tid + 256 * i;
            int l = idx >> 3, pc = (idx & 7) * 4;
            float4 xv = *(const float4*)&g_x[(size_t)(rbase + l) * DI + h * HD + p0 + pc];
            xTs[(pc + 0) * SSTR + l] = f2tf_f(xv.x);
            xTs[(pc + 1) * SSTR + l] = f2tf_f(xv.y);
            xTs[(pc + 2) * SSTR + l] = f2tf_f(xv.z);
            xTs[(pc + 3) * SSTR + l] = f2tf_f(xv.w);
        }
        float decay = g_decay[bhc];
        __syncthreads();
        // ---- y = GM@x + Ce@hT (old h) ----
        float yA[4] = {0.f, 0.f, 0.f, 0.f};
        float yB[4] = {0.f, 0.f, 0.f, 0.f};
        mm_tile(yA, yB, GMs, xTs, mt, nt2, r, cc);
        mm_tile(yA, yB, Ces, hTs, mt, nt2, r, cc);
        {
            int tok = rbase + mt * 16 + r;
            int col = h * HD + p0 + nt2 * 8 + 2 * cc;
            float* y0 = g_y + (size_t)tok * DI + col;
            float* y1 = g_y + (size_t)(tok + 8) * DI + col;
            y0[0] = yA[0]; y0[1] = yA[1];
            y0[8] = yB[0]; y0[9] = yB[1];
            y1[0] = yA[2]; y1[1] = yA[3];
            y1[8] = yB[2]; y1[9] = yB[3];
        }
        // ---- h = decay*h + Btw@x ----
        #pragma unroll
        for (int q = 0; q < 4; q++) { hA[q] *= decay; hB[q] *= decay; }
        mm_tile(hA, hB, Bts, xTs, mt, nt2, r, cc);
        __syncthreads();
        {
            int pp0 = nt2 * 8 + 2 * cc;
            int nn = mt * 16 + r;
            hTs[(pp0 + 0) * SSTR + nn]     = f2tf_f(hA[0]);
            hTs[(pp0 + 1) * SSTR + nn]     = f2tf_f(hA[1]);
            hTs[(pp0 + 0) * SSTR + nn + 8] = f2tf_f(hA[2]);
            hTs[(pp0 + 1) * SSTR + nn + 8] = f2tf_f(hA[3]);
            hTs[(pp0 + 8) * SSTR + nn]     = f2tf_f(hB[0]);
            hTs[(pp0 + 9) * SSTR + nn]     = f2tf_f(hB[1]);
            hTs[(pp0 + 8) * SSTR + nn + 8] = f2tf_f(hB[2]);
            hTs[(pp0 + 9) * SSTR + nn + 8] = f2tf_f(hB[3]);
        }
    }
}

// ------------------------- K5: gate + RMSNorm (tf32-rounded output) -------------------------
__global__ __launch_bounds__(256) void k_gate(const float* __restrict__ Dp,
                                              const float* __restrict__ wno) {
    int row = blockIdx.x, tid = threadIdx.x;
    __shared__ float red[8];
    const float* yr = g_y + (size_t)row * DI;
    const float* xr = g_x + (size_t)row * DI;
    const float* zr = g_proj + (size_t)row * PROJ + OFF_Z;
    float vals[8];
    float ss = 0.f;
    #pragma unroll
    for (int k = 0; k < 8; k++) {
        int cidx = tid + 256 * k;
        int hh = cidx >> 8;
        float y = yr[cidx] + xr[cidx] * Dp[hh];
        float z = zr[cidx];
        float v = y * (z / (1.f + expf(-z)));
        vals[k] = v; ss += v * v;
    }
    ss = blk_reduce_sum(ss, red);
    float sc = rsqrtf(ss * (1.0f / DI) + EPSV);
    float* outp = g_yn + (size_t)row * DI;
    #pragma unroll
    for (int k = 0; k < 8; k++) {
        int cidx = tid + 256 * k;
        outp[cidx] = f2tf_f(vals[k] * sc * wno[cidx]);
    }
}

// ------------------------- launch -------------------------
extern "C" void kernel_launch(void* const* d_in, const int* in_sizes, int n_in,
                              void* d_out, int out_size) {
    const float* hidden = (const float*)d_in[0];
    const float* w_norm_in = (const float*)d_in[1];
    const float* w_in_proj = (const float*)d_in[2];
    const float* conv_w = (const float*)d_in[3];
    const float* conv_b = (const float*)d_in[4];
    const float* w_dt = (const float*)d_in[5];
    const float* b_dt = (const float*)d_in[6];
    const float* A_log = (const float*)d_in[7];
    const float* Dp = (const float*)d_in[8];
    const float* w_norm_out = (const float*)d_in[9];
    const float* w_out_proj = (const float*)d_in[10];
    float* out = (float*)d_out;

    float *p_normed, *p_proj, *p_yn, *p_w1tt, *p_w2tt;
    cudaGetSymbolAddress((void**)&p_normed, g_normed);
    cudaGetSymbolAddress((void**)&p_proj, g_proj);
    cudaGetSymbolAddress((void**)&p_yn, g_yn);
    cudaGetSymbolAddress((void**)&p_w1tt, g_w1tt);
    cudaGetSymbolAddress((void**)&p_w2tt, g_w2tt);

    cudaFuncSetAttribute(k_scan, cudaFuncAttributeMaxDynamicSharedMemorySize, SC_SMEM);
    cudaFuncSetAttribute(gemm_tc, cudaFuncAttributeMaxDynamicSharedMemorySize, GSMEM);

    k_tr<<<dim3(DM / 32, PROJP / 32), 256>>>(w_in_proj, p_w1tt, DM, PROJ);
    k_tr<<<dim3(DI / 32, DM / 32), 256>>>(w_out_proj, p_w2tt, DI, DM);
    k_rms_in<<<ROWS, 256>>>(hidden, w_norm_in);
    gemm_tc<<<dim3(PROJP / 128, ROWS / 256), 256, GSMEM>>>(
        p_normed, p_w1tt, nullptr, p_proj, ROWS, PROJ, DM, 0);
    k_conv<<<dim3(DI / 256, ROWS / 8), 256>>>(conv_w, conv_b);
    k_dt<<<ROWS / 16, 256>>>(w_dt, b_dt);
    k_chunkprep<<<dim3(NC, NH, 2), 256>>>(A_log);
    k_scan<<<dim3(8, NH, 2), 256, SC_SMEM>>>();
    k_gate<<<ROWS, 256>>>(Dp, w_norm_out);
    gemm_tc<<<dim3(DM / 128, ROWS / 256), 256, GSMEM>>>(
        p_yn, p_w2tt, hidden, out, ROWS, DM, DI, 1);
}

// round 8
// speedup vs baseline: 4.1341x; 1.3484x over previous
#include <cuda_runtime.h>
#include <cuda_fp16.h>
#include <cstdint>
#include <math.h>

#define ROWS   8192
#define SEQ    4096
#define DM     1024
#define DI     2048
#define NH     8
#define HD     256
#define NS     64
#define CHK    64
#define NC     64
#define PROJ   5128
#define PROJP  5376
#define OFF_Z  0
#define OFF_X  2048
#define OFF_B  4096
#define OFF_C  4608
#define OFF_DT 5120
#define EPSV   1.1920929e-7f

// ------------------------- scratch (device globals) -------------------------
__device__ __half g_normed[ROWS * DM];             // fp16 rmsnorm output
__device__ float g_proj[(size_t)ROWS * PROJ];
__device__ float g_x[ROWS * DI];
__device__ float g_dt[ROWS * NH];
__device__ float g_GM[1024 * 4096];
__device__ float g_lcse[1024 * 64];
__device__ float g_wl[1024 * 64];
__device__ float g_decay[1024];
__device__ float g_y[ROWS * DI];
__device__ __half g_yn[ROWS * DI];                 // fp16 gated output
__device__ __half g_w1tt[(size_t)PROJP * DM];      // w_in_proj^T fp16, padded
__device__ __half g_w2tt[(size_t)DM * DI];         // w_out_proj^T fp16

// ------------------------- helpers -------------------------
__device__ __forceinline__ float blk_reduce_sum(float v, float* red) {
    int tid = threadIdx.x;
    #pragma unroll
    for (int o = 16; o > 0; o >>= 1) v += __shfl_xor_sync(0xffffffffu, v, o);
    if ((tid & 31) == 0) red[tid >> 5] = v;
    __syncthreads();
    if (tid < 8) {
        float t = red[tid];
        #pragma unroll
        for (int o = 4; o > 0; o >>= 1) t += __shfl_xor_sync(0xffu, t, o);
        if (tid == 0) red[0] = t;
    }
    __syncthreads();
    return red[0];
}

__device__ __forceinline__ float f2tf_f(float f) {
    uint32_t o;
    asm("cvt.rna.tf32.f32 %0, %1;" : "=r"(o) : "f"(f));
    return __uint_as_float(o);
}

__device__ __forceinline__ uint32_t s2u(const void* p) {
    uint32_t a;
    asm("{ .reg .u64 t; cvta.to.shared.u64 t, %1; cvt.u32.u64 %0, t; }"
        : "=r"(a) : "l"(p));
    return a;
}

__device__ __forceinline__ void cp16s(uint32_t d, const void* s) {
    asm volatile("cp.async.cg.shared.global [%0], [%1], 16;\n" :: "r"(d), "l"(s));
}
__device__ __forceinline__ void cp_commit() {
    asm volatile("cp.async.commit_group;\n" ::);
}
template <int N>
__device__ __forceinline__ void cp_wait() {
    asm volatile("cp.async.wait_group %0;\n" :: "n"(N));
}

__device__ __forceinline__ void mma8(float* c, const uint32_t* a, const uint32_t* b) {
    asm volatile(
        "mma.sync.aligned.m16n8k8.row.col.f32.tf32.tf32.f32 "
        "{%0,%1,%2,%3},{%4,%5,%6,%7},{%8,%9},{%0,%1,%2,%3};\n"
        : "+f"(c[0]), "+f"(c[1]), "+f"(c[2]), "+f"(c[3])
        : "r"(a[0]), "r"(a[1]), "r"(a[2]), "r"(a[3]), "r"(b[0]), "r"(b[1]));
}

__device__ __forceinline__ void mma16h(float* c, const uint32_t* a, const uint32_t* b) {
    asm volatile(
        "mma.sync.aligned.m16n8k16.row.col.f32.f16.f16.f32 "
        "{%0,%1,%2,%3},{%4,%5,%6,%7},{%8,%9},{%0,%1,%2,%3};\n"
        : "+f"(c[0]), "+f"(c[1]), "+f"(c[2]), "+f"(c[3])
        : "r"(a[0]), "r"(a[1]), "r"(a[2]), "r"(a[3]), "r"(b[0]), "r"(b[1]));
}

// ------------------------- K0: transpose + fp16 round weights -------------------------
__global__ __launch_bounds__(256) void k_tr(const float* __restrict__ in,
                                            __half* __restrict__ out,
                                            int Kd, int Nin) {
    __shared__ float t[32][33];
    int k0 = blockIdx.x * 32, n0 = blockIdx.y * 32;
    int tx = threadIdx.x & 31, ty = threadIdx.x >> 5;
    #pragma unroll
    for (int i = ty; i < 32; i += 8) {
        int n = n0 + tx;
        t[i][tx] = (n < Nin) ? in[(size_t)(k0 + i) * Nin + n] : 0.f;
    }
    __syncthreads();
    #pragma unroll
    for (int i = ty; i < 32; i += 8)
        out[(size_t)(n0 + i) * Kd + k0 + tx] = __float2half_rn(t[tx][i]);
}

// ------------------------- K1: input RMSNorm (fp16 output) -------------------------
__global__ __launch_bounds__(256) void k_rms_in(const float* __restrict__ hidden,
                                                const float* __restrict__ w) {
    int row = blockIdx.x, tid = threadIdx.x;
    __shared__ float red[8];
    float4 v = ((const float4*)(hidden + (size_t)row * DM))[tid];
    float ss = v.x * v.x + v.y * v.y + v.z * v.z + v.w * v.w;
    ss = blk_reduce_sum(ss, red);
    float sc = rsqrtf(ss * (1.0f / DM) + EPSV);
    float4 wv = ((const float4*)w)[tid];
    __half2 h0 = __floats2half2_rn(v.x * sc * wv.x, v.y * sc * wv.y);
    __half2 h1 = __floats2half2_rn(v.z * sc * wv.z, v.w * sc * wv.w);
    uint2 pk;
    pk.x = *(uint32_t*)&h0;
    pk.y = *(uint32_t*)&h1;
    ((uint2*)(g_normed + (size_t)row * DM))[tid] = pk;
}

// ------------------------- FP16 mma.sync GEMM (m16n8k16) -------------------------
// C[M,N] = A[M,K] @ BT[N,K]^T (+R). BM=256, BN=128, Kstage=32, 3 stages,
// 256 thr (8 warps, 64x64 tiles). k permuted: global 4cc..4cc+3 -> mma slots
// {2cc,2cc+1,2cc+8,2cc+9}; fragments are single LDS.64.
#define HSTR 48
#define A_HALFS (256 * HSTR)
#define B_HALFS (128 * HSTR)
#define STG_HALFS (A_HALFS + B_HALFS)
#define NSTG 3
#define GSMEM (NSTG * STG_HALFS * 2)

__device__ __forceinline__ void fill_stage(const __half* __restrict__ A,
                                           const __half* __restrict__ BT,
                                           __half* __restrict__ sm, int s,
                                           int bm, int bn, int kt, int K, int tid) {
    __half* As = sm + s * STG_HALFS;
    __half* Bs = As + A_HALFS;
    uint32_t ab = s2u(As), bb = s2u(Bs);
    const __half* Ap = A + (size_t)bm * K + kt * 32;
    #pragma unroll
    for (int j = 0; j < 4; j++) {
        int i = tid + 256 * j;
        int row = i >> 2, c = i & 3;
        cp16s(ab + (row * HSTR + c * 8) * 2, Ap + (size_t)row * K + c * 8);
    }
    const __half* Bp = BT + (size_t)bn * K + kt * 32;
    #pragma unroll
    for (int j = 0; j < 2; j++) {
        int i = tid + 256 * j;
        int row = i >> 2, c = i & 3;
        cp16s(bb + (row * HSTR + c * 8) * 2, Bp + (size_t)row * K + c * 8);
    }
}

__global__ __launch_bounds__(256) void gemm_hc(const __half* __restrict__ A,
                                               const __half* __restrict__ BT,
                                               const float* __restrict__ R,
                                               float* __restrict__ C,
                                               int M, int N, int K, int addR) {
    extern __shared__ __half smh[];
    int tid = threadIdx.x, lane = tid & 31, warp = tid >> 5;
    int bm = blockIdx.y * 256, bn = blockIdx.x * 128;
    int wm = (warp >> 1) * 64, wn = (warp & 1) * 64;
    int r = lane >> 2, cc = lane & 3;
    float acc[4][8][4];
    #pragma unroll
    for (int mi = 0; mi < 4; mi++)
        #pragma unroll
        for (int ni = 0; ni < 8; ni++)
            #pragma unroll
            for (int q = 0; q < 4; q++) acc[mi][ni][q] = 0.f;

    int nk = K >> 5;
    #pragma unroll
    for (int s = 0; s < NSTG; s++) {
        fill_stage(A, BT, smh, s, bm, bn, s, K, tid);
        cp_commit();
    }

    for (int kt = 0; kt < nk; kt++) {
        int s = kt % NSTG;
        cp_wait<NSTG - 1>();
        __syncthreads();
        const __half* As = smh + s * STG_HALFS;
        const __half* Bs = As + A_HALFS;
        const __half* arow = As + (wm + r) * HSTR + 4 * cc;
        const __half* brow = Bs + (wn + r) * HSTR + 4 * cc;
        #pragma unroll
        for (int s16 = 0; s16 < 32; s16 += 16) {
            uint32_t af[4][4];
            #pragma unroll
            for (int mi = 0; mi < 4; mi++) {
                uint2 v0 = *(const uint2*)(arow + mi * 16 * HSTR + s16);
                uint2 v1 = *(const uint2*)(arow + (mi * 16 + 8) * HSTR + s16);
                af[mi][0] = v0.x; af[mi][1] = v1.x;
                af[mi][2] = v0.y; af[mi][3] = v1.y;
            }
            uint32_t bf[8][2];
            #pragma unroll
            for (int ni = 0; ni < 8; ni++) {
                uint2 w = *(const uint2*)(brow + ni * 8 * HSTR + s16);
                bf[ni][0] = w.x; bf[ni][1] = w.y;
            }
            #pragma unroll
            for (int mi = 0; mi < 4; mi++)
                #pragma unroll
                for (int ni = 0; ni < 8; ni++)
                    mma16h(acc[mi][ni], af[mi], bf[ni]);
        }
        __syncthreads();
        if (kt + NSTG < nk) {
            fill_stage(A, BT, smh, s, bm, bn, kt + NSTG, K, tid);
            cp_commit();
        } else {
            cp_commit();
        }
    }

    #pragma unroll
    for (int mi = 0; mi < 4; mi++) {
        int row = bm + wm + mi * 16 + r;
        #pragma unroll
        for (int ni = 0; ni < 8; ni++) {
            int col = bn + wn + ni * 8 + 2 * cc;
            if (col < N) {
                size_t o0 = (size_t)row * N + col;
                size_t o1 = (size_t)(row + 8) * N + col;
                float2 v0 = make_float2(acc[mi][ni][0], acc[mi][ni][1]);
                float2 v1 = make_float2(acc[mi][ni][2], acc[mi][ni][3]);
                if (addR) {
                    float2 r0 = *(const float2*)(R + o0);
                    float2 r1 = *(const float2*)(R + o1);
                    v0.x += r0.x; v0.y += r0.y;
                    v1.x += r1.x; v1.y += r1.y;
                }
                *(float2*)(C + o0) = v0;
                *(float2*)(C + o1) = v1;
            }
        }
    }
}

// ------------------------- K3: causal depthwise conv + SiLU (rolling window) -------------------------
__global__ __launch_bounds__(256) void k_conv(const float* __restrict__ cw,
                                              const float* __restrict__ cb) {
    int c = blockIdx.x * 256 + threadIdx.x;
    int row0 = blockIdx.y * 8;
    int s0 = row0 & (SEQ - 1);
    float w0 = cw[c * 4 + 0], w1 = cw[c * 4 + 1], w2 = cw[c * 4 + 2], w3 = cw[c * 4 + 3];
    const float* xp = g_proj + (size_t)row0 * PROJ + OFF_X + c;
    float x0 = (s0 >= 3) ? xp[-3 * (int)PROJ] : 0.f;
    float x1 = (s0 >= 2) ? xp[-2 * (int)PROJ] : 0.f;
    float x2 = (s0 >= 1) ? xp[-(int)PROJ] : 0.f;
    float bias = cb[c];
    #pragma unroll
    for (int k = 0; k < 8; k++) {
        float x3 = xp[(size_t)k * PROJ];
        float acc = bias + w0 * x0 + w1 * x1 + w2 * x2 + w3 * x3;
        g_x[(size_t)(row0 + k) * DI + c] = acc / (1.f + expf(-acc));
        x0 = x1; x1 = x2; x2 = x3;
    }
}

// ------------------------- K3b: dt -------------------------
__global__ __launch_bounds__(256) void k_dt(const float* __restrict__ wdt,
                                            const float* __restrict__ bdt) {
    int tid = threadIdx.x;
    int h = tid >> 5, lane = tid & 31;
    int d0 = h * HD + lane * 8;
    float w[8][8], bb[8];
    #pragma unroll
    for (int j = 0; j < 8; j++)
        #pragma unroll
        for (int q = 0; q < 8; q++) w[j][q] = wdt[j * DI + d0 + q];
    #pragma unroll
    for (int q = 0; q < 8; q++) bb[q] = bdt[d0 + q];

    int row0 = blockIdx.x * 16;
    for (int rr = 0; rr < 16; rr++) {
        int row = row0 + rr;
        const float* pr = g_proj + (size_t)row * PROJ + OFF_DT;
        float dtr[8];
        #pragma unroll
        for (int j = 0; j < 8; j++) dtr[j] = pr[j];
        float acc = 0.f;
        #pragma unroll
        for (int q = 0; q < 8; q++) {
            float v = bb[q];
            #pragma unroll
            for (int j = 0; j < 8; j++) v += dtr[j] * w[j][q];
            acc += (v > 20.f) ? v : log1pf(expf(v));
        }
        #pragma unroll
        for (int o = 16; o > 0; o >>= 1) acc += __shfl_xor_sync(0xffffffffu, acc, o);
        if (lane == 0) g_dt[row * NH + h] = acc * (1.0f / HD);
    }
}

// ------------------------- K4a: chunk prep -------------------------
__global__ __launch_bounds__(256) void k_chunkprep(const float* __restrict__ A_log) {
    int c = blockIdx.x, h = blockIdx.y, b = blockIdx.z;
    int bhc = (b * NH + h) * NC + c;
    int rbase = b * SEQ + c * CHK;
    __shared__ float Bc[64 * 68];
    __shared__ float Cc[64 * 68];
    __shared__ float lcs[64];
    __shared__ float sdt[64];
    int tid = threadIdx.x;
    float A = -expf(A_log[h]);
    if (tid < 64) sdt[tid] = g_dt[(rbase + tid) * NH + h] * A;
    #pragma unroll
    for (int i = 0; i < 4; i++) {
        int f = (tid + 256 * i) * 4;
        int l = f >> 6, n = f & 63;
        const float* pr = g_proj + (size_t)(rbase + l) * PROJ;
        float4 bv = *(const float4*)(pr + OFF_B + h * NS + n);
        float4 cv = *(const float4*)(pr + OFF_C + h * NS + n);
        Bc[l * 68 + n + 0] = bv.x; Bc[l * 68 + n + 1] = bv.y;
        Bc[l * 68 + n + 2] = bv.z; Bc[l * 68 + n + 3] = bv.w;
        Cc[l * 68 + n + 0] = cv.x; Cc[l * 68 + n + 1] = cv.y;
        Cc[l * 68 + n + 2] = cv.z; Cc[l * 68 + n + 3] = cv.w;
    }
    __syncthreads();
    if (tid == 0) {
        float run = 0.f;
        for (int l = 0; l < 64; l++) { run += sdt[l]; lcs[l] = run; }
    }
    __syncthreads();
    float lcs63 = lcs[63];
    int l = tid >> 2, i0 = (tid & 3) * 16;
    float* outp = g_GM + (size_t)bhc * 4096;
    float myl = lcs[l];
    for (int q = 0; q < 16; q++) {
        int i = i0 + q;
        float g = 0.f;
        #pragma unroll
        for (int n = 0; n < 64; n++) g += Cc[l * 68 + n] * Bc[i * 68 + n];
        float m = (i <= l) ? expf(myl - lcs[i]) : 0.f;
        outp[l * 64 + i] = m * g;
    }
    if (tid < 64) {
        g_lcse[bhc * 64 + tid] = expf(lcs[tid]);
        g_wl[bhc * 64 + tid] = expf(lcs63 - lcs[tid]);
    }
    if (tid == 0) g_decay[bhc] = expf(lcs63);
}

// ------------------------- K4b: mma-based sequential chunk scan -------------------------
#define SSTR 72
#define SC_GM   0
#define SC_CE   (64 * SSTR)
#define SC_BT   (2 * 64 * SSTR)
#define SC_XT   (3 * 64 * SSTR)
#define SC_HT   (3 * 64 * SSTR + 32 * SSTR)
#define SC_SMEM ((3 * 64 + 2 * 32) * SSTR * 4)

__device__ __forceinline__ void mm_tile(float* accA, float* accB,
                                        const float* Asm, const float* Bsm,
                                        int mt, int nt2, int r, int cc) {
    const float* ap = Asm + (mt * 16 + r) * SSTR + 2 * cc;
    const float* bp0 = Bsm + (nt2 * 8 + r) * SSTR + 2 * cc;
    const float* bp1 = bp0 + 8 * SSTR;
    #pragma unroll
    for (int k8 = 0; k8 < 64; k8 += 8) {
        float2 a0 = *(const float2*)(ap + k8);
        float2 a1 = *(const float2*)(ap + 8 * SSTR + k8);
        uint32_t af[4] = {__float_as_uint(a0.x), __float_as_uint(a1.x),
                          __float_as_uint(a0.y), __float_as_uint(a1.y)};
        float2 b0 = *(const float2*)(bp0 + k8);
        float2 b1 = *(const float2*)(bp1 + k8);
        uint32_t bf0[2] = {__float_as_uint(b0.x), __float_as_uint(b0.y)};
        uint32_t bf1[2] = {__float_as_uint(b1.x), __float_as_uint(b1.y)};
        mma8(accA, af, bf0);
        mma8(accB, af, bf1);
    }
}

__global__ __launch_bounds__(256) void k_scan() {
    extern __shared__ float sm[];
    float* GMs = sm + SC_GM;
    float* Ces = sm + SC_CE;
    float* Bts = sm + SC_BT;
    float* xTs = sm + SC_XT;
    float* hTs = sm + SC_HT;
    int tid = threadIdx.x, lane = tid & 31, w = tid >> 5;
    int pt = blockIdx.x, h = blockIdx.y, b = blockIdx.z;
    int p0 = pt * 32, bh = b * NH + h;
    int r = lane >> 2, cc = lane & 3;
    int mt = w & 3, nt2 = (w >> 2) * 2;

    for (int e = tid; e < 32 * SSTR; e += 256) hTs[e] = 0.f;
    float hA[4] = {0.f, 0.f, 0.f, 0.f};
    float hB[4] = {0.f, 0.f, 0.f, 0.f};

    for (int c = 0; c < NC; c++) {
        int bhc = bh * NC + c;
        int rbase = b * SEQ + c * CHK;
        __syncthreads();
        const float* gmp = g_GM + (size_t)bhc * 4096;
        const float* lcp = g_lcse + bhc * 64;
        const float* wlp = g_wl + bhc * 64;
        #pragma unroll
        for (int i = 0; i < 4; i++) {
            int f4 = (tid + 256 * i) * 4;
            int l = f4 >> 6, n = f4 & 63;
            float4 gv = *(const float4*)&gmp[f4];
            gv.x = f2tf_f(gv.x); gv.y = f2tf_f(gv.y);
            gv.z = f2tf_f(gv.z); gv.w = f2tf_f(gv.w);
            *(float4*)&GMs[l * SSTR + n] = gv;
            const float* pr = g_proj + (size_t)(rbase + l) * PROJ;
            float lc = lcp[l];
            float4 cv = *(const float4*)(pr + OFF_C + h * NS + n);
            cv.x = f2tf_f(cv.x * lc); cv.y = f2tf_f(cv.y * lc);
            cv.z = f2tf_f(cv.z * lc); cv.w = f2tf_f(cv.w * lc);
            *(float4*)&Ces[l * SSTR + n] = cv;
            float wl = wlp[l];
            float4 bv = *(const float4*)(pr + OFF_B + h * NS + n);
            Bts[(n + 0) * SSTR + l] = f2tf_f(bv.x * wl);
            Bts[(n + 1) * SSTR + l] = f2tf_f(bv.y * wl);
            Bts[(n + 2) * SSTR + l] = f2tf_f(bv.z * wl);
            Bts[(n + 3) * SSTR + l] = f2tf_f(bv.w * wl);
        }
        #pragma unroll
        for (int i = 0; i < 2; i++) {
            int idx = tid + 256 * i;
            int l = idx >> 3, pc = (idx & 7) * 4;
            float4 xv = *(const float4*)&g_x[(size_t)(rbase + l) * DI + h * HD + p0 + pc];
            xTs[(pc + 0) * SSTR + l] = f2tf_f(xv.x);
            xTs[(pc + 1) * SSTR + l] = f2tf_f(xv.y);
            xTs[(pc + 2) * SSTR + l] = f2tf_f(xv.z);
            xTs[(pc + 3) * SSTR + l] = f2tf_f(xv.w);
        }
        float decay = g_decay[bhc];
        __syncthreads();
        float yA[4] = {0.f, 0.f, 0.f, 0.f};
        float yB[4] = {0.f, 0.f, 0.f, 0.f};
        mm_tile(yA, yB, GMs, xTs, mt, nt2, r, cc);
        mm_tile(yA, yB, Ces, hTs, mt, nt2, r, cc);
        {
            int tok = rbase + mt * 16 + r;
            int col = h * HD + p0 + nt2 * 8 + 2 * cc;
            float* y0 = g_y + (size_t)tok * DI + col;
            float* y1 = g_y + (size_t)(tok + 8) * DI + col;
            y0[0] = yA[0]; y0[1] = yA[1];
            y0[8] = yB[0]; y0[9] = yB[1];
            y1[0] = yA[2]; y1[1] = yA[3];
            y1[8] = yB[2]; y1[9] = yB[3];
        }
        #pragma unroll
        for (int q = 0; q < 4; q++) { hA[q] *= decay; hB[q] *= decay; }
        mm_tile(hA, hB, Bts, xTs, mt, nt2, r, cc);
        __syncthreads();
        {
            int pp0 = nt2 * 8 + 2 * cc;
            int nn = mt * 16 + r;
            hTs[(pp0 + 0) * SSTR + nn]     = f2tf_f(hA[0]);
            hTs[(pp0 + 1) * SSTR + nn]     = f2tf_f(hA[1]);
            hTs[(pp0 + 0) * SSTR + nn + 8] = f2tf_f(hA[2]);
            hTs[(pp0 + 1) * SSTR + nn + 8] = f2tf_f(hA[3]);
            hTs[(pp0 + 8) * SSTR + nn]     = f2tf_f(hB[0]);
            hTs[(pp0 + 9) * SSTR + nn]     = f2tf_f(hB[1]);
            hTs[(pp0 + 8) * SSTR + nn + 8] = f2tf_f(hB[2]);
            hTs[(pp0 + 9) * SSTR + nn + 8] = f2tf_f(hB[3]);
        }
    }
}

// ------------------------- K5: gate + RMSNorm (fp16 output) -------------------------
__global__ __launch_bounds__(256) void k_gate(const float* __restrict__ Dp,
                                              const float* __restrict__ wno) {
    int row = blockIdx.x, tid = threadIdx.x;
    __shared__ float red[8];
    const float* yr = g_y + (size_t)row * DI;
    const float* xr = g_x + (size_t)row * DI;
    const float* zr = g_proj + (size_t)row * PROJ + OFF_Z;
    float vals[8];
    float ss = 0.f;
    #pragma unroll
    for (int k = 0; k < 8; k++) {
        int cidx = tid + 256 * k;
        int hh = cidx >> 8;
        float y = yr[cidx] + xr[cidx] * Dp[hh];
        float z = zr[cidx];
        float v = y * (z / (1.f + expf(-z)));
        vals[k] = v; ss += v * v;
    }
    ss = blk_reduce_sum(ss, red);
    float sc = rsqrtf(ss * (1.0f / DI) + EPSV);
    __half* outp = g_yn + (size_t)row * DI;
    #pragma unroll
    for (int k = 0; k < 8; k++) {
        int cidx = tid + 256 * k;
        outp[cidx] = __float2half_rn(vals[k] * sc * wno[cidx]);
    }
}

// ------------------------- launch -------------------------
extern "C" void kernel_launch(void* const* d_in, const int* in_sizes, int n_in,
                              void* d_out, int out_size) {
    const float* hidden = (const float*)d_in[0];
    const float* w_norm_in = (const float*)d_in[1];
    const float* w_in_proj = (const float*)d_in[2];
    const float* conv_w = (const float*)d_in[3];
    const float* conv_b = (const float*)d_in[4];
    const float* w_dt = (const float*)d_in[5];
    const float* b_dt = (const float*)d_in[6];
    const float* A_log = (const float*)d_in[7];
    const float* Dp = (const float*)d_in[8];
    const float* w_norm_out = (const float*)d_in[9];
    const float* w_out_proj = (const float*)d_in[10];
    float* out = (float*)d_out;

    float *p_proj;
    __half *p_normed, *p_yn, *p_w1tt, *p_w2tt;
    cudaGetSymbolAddress((void**)&p_normed, g_normed);
    cudaGetSymbolAddress((void**)&p_proj, g_proj);
    cudaGetSymbolAddress((void**)&p_yn, g_yn);
    cudaGetSymbolAddress((void**)&p_w1tt, g_w1tt);
    cudaGetSymbolAddress((void**)&p_w2tt, g_w2tt);

    cudaFuncSetAttribute(k_scan, cudaFuncAttributeMaxDynamicSharedMemorySize, SC_SMEM);
    cudaFuncSetAttribute(gemm_hc, cudaFuncAttributeMaxDynamicSharedMemorySize, GSMEM);

    k_tr<<<dim3(DM / 32, PROJP / 32), 256>>>(w_in_proj, p_w1tt, DM, PROJ);
    k_tr<<<dim3(DI / 32, DM / 32), 256>>>(w_out_proj, p_w2tt, DI, DM);
    k_rms_in<<<ROWS, 256>>>(hidden, w_norm_in);
    gemm_hc<<<dim3(PROJP / 128, ROWS / 256), 256, GSMEM>>>(
        p_normed, p_w1tt, nullptr, p_proj, ROWS, PROJ, DM, 0);
    k_conv<<<dim3(DI / 256, ROWS / 8), 256>>>(conv_w, conv_b);
    k_dt<<<ROWS / 16, 256>>>(w_dt, b_dt);
    k_chunkprep<<<dim3(NC, NH, 2), 256>>>(A_log);
    k_scan<<<dim3(8, NH, 2), 256, SC_SMEM>>>();
    k_gate<<<ROWS, 256>>>(Dp, w_norm_out);
    gemm_hc<<<dim3(DM / 128, ROWS / 256), 256, GSMEM>>>(
        p_yn, p_w2tt, hidden, out, ROWS, DM, DI, 1);
}

// round 9
// speedup vs baseline: 4.4857x; 1.0850x over previous
#include <cuda_runtime.h>
#include <cuda_fp16.h>
#include <cstdint>
#include <math.h>

#define ROWS   8192
#define SEQ    4096
#define DM     1024
#define DI     2048
#define NH     8
#define HD     256
#define NS     64
#define CHK    64
#define NC     64
#define PROJ   5128
#define PROJP  5376
#define OFF_Z  0
#define OFF_X  2048
#define OFF_B  4096
#define OFF_C  4608
#define OFF_DT 5120
#define EPSV   1.1920929e-7f

// ------------------------- scratch (device globals) -------------------------
__device__ __half g_normed[ROWS * DM];
__device__ float g_proj[(size_t)ROWS * PROJ];
__device__ float g_x[ROWS * DI];
__device__ float g_dt[ROWS * NH];
__device__ float g_GM[1024 * 4096];
__device__ float g_lcse[1024 * 64];
__device__ float g_wl[1024 * 64];
__device__ float g_decay[1024];
__device__ float g_y[ROWS * DI];
__device__ __half g_yn[ROWS * DI];
__device__ __half g_w1tt[(size_t)PROJP * DM];
__device__ __half g_w2tt[(size_t)DM * DI];

// ------------------------- helpers -------------------------
__device__ __forceinline__ float blk_reduce_sum(float v, float* red) {
    int tid = threadIdx.x;
    #pragma unroll
    for (int o = 16; o > 0; o >>= 1) v += __shfl_xor_sync(0xffffffffu, v, o);
    if ((tid & 31) == 0) red[tid >> 5] = v;
    __syncthreads();
    if (tid < 8) {
        float t = red[tid];
        #pragma unroll
        for (int o = 4; o > 0; o >>= 1) t += __shfl_xor_sync(0xffu, t, o);
        if (tid == 0) red[0] = t;
    }
    __syncthreads();
    return red[0];
}

__device__ __forceinline__ float silu_f(float x) {
    return x / (1.f + __expf(-x));
}

__device__ __forceinline__ uint32_t s2u(const void* p) {
    uint32_t a;
    asm("{ .reg .u64 t; cvta.to.shared.u64 t, %1; cvt.u32.u64 %0, t; }"
        : "=r"(a) : "l"(p));
    return a;
}

__device__ __forceinline__ void cp16s(uint32_t d, const void* s) {
    asm volatile("cp.async.cg.shared.global [%0], [%1], 16;\n" :: "r"(d), "l"(s));
}
__device__ __forceinline__ void cp_commit() {
    asm volatile("cp.async.commit_group;\n" ::);
}
template <int N>
__device__ __forceinline__ void cp_wait() {
    asm volatile("cp.async.wait_group %0;\n" :: "n"(N));
}

__device__ __forceinline__ void mma16h(float* c, const uint32_t* a, const uint32_t* b) {
    asm volatile(
        "mma.sync.aligned.m16n8k16.row.col.f32.f16.f16.f32 "
        "{%0,%1,%2,%3},{%4,%5,%6,%7},{%8,%9},{%0,%1,%2,%3};\n"
        : "+f"(c[0]), "+f"(c[1]), "+f"(c[2]), "+f"(c[3])
        : "r"(a[0]), "r"(a[1]), "r"(a[2]), "r"(a[3]), "r"(b[0]), "r"(b[1]));
}

// ------------------------- K0: transpose + fp16 round weights -------------------------
__global__ __launch_bounds__(256) void k_tr(const float* __restrict__ in,
                                            __half* __restrict__ out,
                                            int Kd, int Nin) {
    __shared__ float t[32][33];
    int k0 = blockIdx.x * 32, n0 = blockIdx.y * 32;
    int tx = threadIdx.x & 31, ty = threadIdx.x >> 5;
    #pragma unroll
    for (int i = ty; i < 32; i += 8) {
        int n = n0 + tx;
        t[i][tx] = (n < Nin) ? in[(size_t)(k0 + i) * Nin + n] : 0.f;
    }
    __syncthreads();
    #pragma unroll
    for (int i = ty; i < 32; i += 8)
        out[(size_t)(n0 + i) * Kd + k0 + tx] = __float2half_rn(t[tx][i]);
}

// ------------------------- K1: input RMSNorm (fp16 output) -------------------------
__global__ __launch_bounds__(256) void k_rms_in(const float* __restrict__ hidden,
                                                const float* __restrict__ w) {
    int row = blockIdx.x, tid = threadIdx.x;
    __shared__ float red[8];
    float4 v = ((const float4*)(hidden + (size_t)row * DM))[tid];
    float ss = v.x * v.x + v.y * v.y + v.z * v.z + v.w * v.w;
    ss = blk_reduce_sum(ss, red);
    float sc = rsqrtf(ss * (1.0f / DM) + EPSV);
    float4 wv = ((const float4*)w)[tid];
    __half2 h0 = __floats2half2_rn(v.x * sc * wv.x, v.y * sc * wv.y);
    __half2 h1 = __floats2half2_rn(v.z * sc * wv.z, v.w * sc * wv.w);
    uint2 pk;
    pk.x = *(uint32_t*)&h0;
    pk.y = *(uint32_t*)&h1;
    ((uint2*)(g_normed + (size_t)row * DM))[tid] = pk;
}

// ------------------------- FP16 mma GEMM: BM=BN=128, 128 thr, 4 stages -------------------------
#define HSTR 48
#define A_HALFS (128 * HSTR)
#define B_HALFS (128 * HSTR)
#define STG_HALFS (A_HALFS + B_HALFS)
#define NSTG 4
#define GSMEM (NSTG * STG_HALFS * 2)

__device__ __forceinline__ void fill_stage(const __half* __restrict__ A,
                                           const __half* __restrict__ BT,
                                           __half* __restrict__ sm, int s,
                                           int bm, int bn, int kt, int K, int tid) {
    __half* As = sm + s * STG_HALFS;
    __half* Bs = As + A_HALFS;
    uint32_t ab = s2u(As), bb = s2u(Bs);
    const __half* Ap = A + (size_t)bm * K + kt * 32;
    #pragma unroll
    for (int j = 0; j < 4; j++) {
        int i = tid + 128 * j;
        int row = i >> 2, c = i & 3;
        cp16s(ab + (row * HSTR + c * 8) * 2, Ap + (size_t)row * K + c * 8);
    }
    const __half* Bp = BT + (size_t)bn * K + kt * 32;
    #pragma unroll
    for (int j = 0; j < 4; j++) {
        int i = tid + 128 * j;
        int row = i >> 2, c = i & 3;
        cp16s(bb + (row * HSTR + c * 8) * 2, Bp + (size_t)row * K + c * 8);
    }
}

__global__ __launch_bounds__(128, 2) void gemm_hc(const __half* __restrict__ A,
                                                  const __half* __restrict__ BT,
                                                  const float* __restrict__ R,
                                                  float* __restrict__ C,
                                                  int M, int N, int K, int addR) {
    extern __shared__ __half smh[];
    int tid = threadIdx.x, lane = tid & 31, warp = tid >> 5;
    int bm = blockIdx.y * 128, bn = blockIdx.x * 128;
    int wm = (warp >> 1) * 64, wn = (warp & 1) * 64;
    int r = lane >> 2, cc = lane & 3;
    float acc[4][8][4];
    #pragma unroll
    for (int mi = 0; mi < 4; mi++)
        #pragma unroll
        for (int ni = 0; ni < 8; ni++)
            #pragma unroll
            for (int q = 0; q < 4; q++) acc[mi][ni][q] = 0.f;

    int nk = K >> 5;
    #pragma unroll
    for (int s = 0; s < NSTG; s++) {
        fill_stage(A, BT, smh, s, bm, bn, s, K, tid);
        cp_commit();
    }

    for (int kt = 0; kt < nk; kt++) {
        int s = kt & (NSTG - 1);
        cp_wait<NSTG - 1>();
        __syncthreads();
        const __half* As = smh + s * STG_HALFS;
        const __half* Bs = As + A_HALFS;
        const __half* arow = As + (wm + r) * HSTR + 4 * cc;
        const __half* brow = Bs + (wn + r) * HSTR + 4 * cc;
        #pragma unroll
        for (int s16 = 0; s16 < 32; s16 += 16) {
            uint32_t af[4][4];
            #pragma unroll
            for (int mi = 0; mi < 4; mi++) {
                uint2 v0 = *(const uint2*)(arow + mi * 16 * HSTR + s16);
                uint2 v1 = *(const uint2*)(arow + (mi * 16 + 8) * HSTR + s16);
                af[mi][0] = v0.x; af[mi][1] = v1.x;
                af[mi][2] = v0.y; af[mi][3] = v1.y;
            }
            uint32_t bf[8][2];
            #pragma unroll
            for (int ni = 0; ni < 8; ni++) {
                uint2 w = *(const uint2*)(brow + ni * 8 * HSTR + s16);
                bf[ni][0] = w.x; bf[ni][1] = w.y;
            }
            #pragma unroll
            for (int mi = 0; mi < 4; mi++)
                #pragma unroll
                for (int ni = 0; ni < 8; ni++)
                    mma16h(acc[mi][ni], af[mi], bf[ni]);
        }
        __syncthreads();
        if (kt + NSTG < nk) {
            fill_stage(A, BT, smh, s, bm, bn, kt + NSTG, K, tid);
            cp_commit();
        } else {
            cp_commit();
        }
    }

    #pragma unroll
    for (int mi = 0; mi < 4; mi++) {
        int row = bm + wm + mi * 16 + r;
        #pragma unroll
        for (int ni = 0; ni < 8; ni++) {
            int col = bn + wn + ni * 8 + 2 * cc;
            if (col < N) {
                size_t o0 = (size_t)row * N + col;
                size_t o1 = (size_t)(row + 8) * N + col;
                float2 v0 = make_float2(acc[mi][ni][0], acc[mi][ni][1]);
                float2 v1 = make_float2(acc[mi][ni][2], acc[mi][ni][3]);
                if (addR) {
                    float2 r0 = *(const float2*)(R + o0);
                    float2 r1 = *(const float2*)(R + o1);
                    v0.x += r0.x; v0.y += r0.y;
                    v1.x += r1.x; v1.y += r1.y;
                }
                *(float2*)(C + o0) = v0;
                *(float2*)(C + o1) = v1;
            }
        }
    }
}

// ------------------------- K3: causal depthwise conv + SiLU (rolling window) -------------------------
__global__ __launch_bounds__(256) void k_conv(const float* __restrict__ cw,
                                              const float* __restrict__ cb) {
    int c = blockIdx.x * 256 + threadIdx.x;
    int row0 = blockIdx.y * 8;
    int s0 = row0 & (SEQ - 1);
    float w0 = cw[c * 4 + 0], w1 = cw[c * 4 + 1], w2 = cw[c * 4 + 2], w3 = cw[c * 4 + 3];
    const float* xp = g_proj + (size_t)row0 * PROJ + OFF_X + c;
    float x0 = (s0 >= 3) ? xp[-3 * (int)PROJ] : 0.f;
    float x1 = (s0 >= 2) ? xp[-2 * (int)PROJ] : 0.f;
    float x2 = (s0 >= 1) ? xp[-(int)PROJ] : 0.f;
    float bias = cb[c];
    #pragma unroll
    for (int k = 0; k < 8; k++) {
        float x3 = xp[(size_t)k * PROJ];
        float acc = bias + w0 * x0 + w1 * x1 + w2 * x2 + w3 * x3;
        g_x[(size_t)(row0 + k) * DI + c] = silu_f(acc);
        x0 = x1; x1 = x2; x2 = x3;
    }
}

// ------------------------- K3b: dt -------------------------
__global__ __launch_bounds__(256) void k_dt(const float* __restrict__ wdt,
                                            const float* __restrict__ bdt) {
    int tid = threadIdx.x;
    int h = tid >> 5, lane = tid & 31;
    int d0 = h * HD + lane * 8;
    float w[8][8], bb[8];
    #pragma unroll
    for (int j = 0; j < 8; j++)
        #pragma unroll
        for (int q = 0; q < 8; q++) w[j][q] = wdt[j * DI + d0 + q];
    #pragma unroll
    for (int q = 0; q < 8; q++) bb[q] = bdt[d0 + q];

    int row0 = blockIdx.x * 16;
    for (int rr = 0; rr < 16; rr++) {
        int row = row0 + rr;
        const float* pr = g_proj + (size_t)row * PROJ + OFF_DT;
        float dtr[8];
        #pragma unroll
        for (int j = 0; j < 8; j++) dtr[j] = pr[j];
        float acc = 0.f;
        #pragma unroll
        for (int q = 0; q < 8; q++) {
            float v = bb[q];
            #pragma unroll
            for (int j = 0; j < 8; j++) v += dtr[j] * w[j][q];
            acc += (v > 15.f) ? v : __logf(1.f + __expf(v));
        }
        #pragma unroll
        for (int o = 16; o > 0; o >>= 1) acc += __shfl_xor_sync(0xffffffffu, acc, o);
        if (lane == 0) g_dt[row * NH + h] = acc * (1.0f / HD);
    }
}

// ------------------------- K4a: chunk prep -------------------------
__global__ __launch_bounds__(256) void k_chunkprep(const float* __restrict__ A_log) {
    int c = blockIdx.x, h = blockIdx.y, b = blockIdx.z;
    int bhc = (b * NH + h) * NC + c;
    int rbase = b * SEQ + c * CHK;
    __shared__ float Bc[64 * 68];
    __shared__ float Cc[64 * 68];
    __shared__ float lcs[64];
    __shared__ float sdt[64];
    int tid = threadIdx.x;
    float A = -__expf(A_log[h]);
    if (tid < 64) sdt[tid] = g_dt[(rbase + tid) * NH + h] * A;
    #pragma unroll
    for (int i = 0; i < 4; i++) {
        int f = (tid + 256 * i) * 4;
        int l = f >> 6, n = f & 63;
        const float* pr = g_proj + (size_t)(rbase + l) * PROJ;
        float4 bv = *(const float4*)(pr + OFF_B + h * NS + n);
        float4 cv = *(const float4*)(pr + OFF_C + h * NS + n);
        Bc[l * 68 + n + 0] = bv.x; Bc[l * 68 + n + 1] = bv.y;
        Bc[l * 68 + n + 2] = bv.z; Bc[l * 68 + n + 3] = bv.w;
        Cc[l * 68 + n + 0] = cv.x; Cc[l * 68 + n + 1] = cv.y;
        Cc[l * 68 + n + 2] = cv.z; Cc[l * 68 + n + 3] = cv.w;
    }
    __syncthreads();
    if (tid == 0) {
        float run = 0.f;
        for (int l = 0; l < 64; l++) { run += sdt[l]; lcs[l] = run; }
    }
    __syncthreads();
    float lcs63 = lcs[63];
    int l = tid >> 2, i0 = (tid & 3) * 16;
    float* outp = g_GM + (size_t)bhc * 4096;
    float myl = lcs[l];
    for (int q = 0; q < 16; q++) {
        int i = i0 + q;
        float g = 0.f;
        #pragma unroll
        for (int n = 0; n < 64; n++) g += Cc[l * 68 + n] * Bc[i * 68 + n];
        float m = (i <= l) ? __expf(myl - lcs[i]) : 0.f;
        outp[l * 64 + i] = m * g;
    }
    if (tid < 64) {
        g_lcse[bhc * 64 + tid] = __expf(lcs[tid]);
        g_wl[bhc * 64 + tid] = __expf(lcs63 - lcs[tid]);
    }
    if (tid == 0) g_decay[bhc] = __expf(lcs63);
}

// ------------------------- K4b: fp16 mma sequential chunk scan -------------------------
// grid (8 p-tiles, NH, 2). 256 thr (8 warps). Stride 80 halves (160B ≡ 32 mod 128:
// phase-conflict-free for uint2 fragment loads).
#define SSH 80
#define SC_GM   0
#define SC_CE   (64 * SSH)
#define SC_BT   (2 * 64 * SSH)
#define SC_XT   (3 * 64 * SSH)
#define SC_HT   (3 * 64 * SSH + 32 * SSH)
#define SC_SMEM ((3 * 64 + 2 * 32) * SSH * 2)

__device__ __forceinline__ void mm_tile_h(float* accA, float* accB,
                                          const __half* Asm, const __half* Bsm,
                                          int mt, int nt2, int r, int cc) {
    const __half* ap = Asm + (mt * 16 + r) * SSH + 4 * cc;
    const __half* bp0 = Bsm + (nt2 * 8 + r) * SSH + 4 * cc;
    const __half* bp1 = bp0 + 8 * SSH;
    #pragma unroll
    for (int s16 = 0; s16 < 64; s16 += 16) {
        uint2 a0 = *(const uint2*)(ap + s16);
        uint2 a1 = *(const uint2*)(ap + 8 * SSH + s16);
        uint32_t af[4] = {a0.x, a1.x, a0.y, a1.y};
        uint2 b0 = *(const uint2*)(bp0 + s16);
        uint2 b1 = *(const uint2*)(bp1 + s16);
        uint32_t bf0[2] = {b0.x, b0.y};
        uint32_t bf1[2] = {b1.x, b1.y};
        mma16h(accA, af, bf0);
        mma16h(accB, af, bf1);
    }
}

__global__ __launch_bounds__(256) void k_scan() {
    extern __shared__ __half smH[];
    __half* GMs = smH + SC_GM;
    __half* Ces = smH + SC_CE;
    __half* Bts = smH + SC_BT;
    __half* xTs = smH + SC_XT;
    __half* hTs = smH + SC_HT;
    int tid = threadIdx.x, lane = tid & 31, w = tid >> 5;
    int pt = blockIdx.x, h = blockIdx.y, b = blockIdx.z;
    int p0 = pt * 32, bh = b * NH + h;
    int r = lane >> 2, cc = lane & 3;
    int mt = w & 3, nt2 = (w >> 2) * 2;

    for (int e = tid; e < 32 * SSH; e += 256) hTs[e] = __float2half_rn(0.f);
    float hA[4] = {0.f, 0.f, 0.f, 0.f};
    float hB[4] = {0.f, 0.f, 0.f, 0.f};

    for (int c = 0; c < NC; c++) {
        int bhc = bh * NC + c;
        int rbase = b * SEQ + c * CHK;
        __syncthreads();
        // ---- load/convert phase ----
        const float* gmp = g_GM + (size_t)bhc * 4096;
        const float* lcp = g_lcse + bhc * 64;
        const float* wlp = g_wl + bhc * 64;
        #pragma unroll
        for (int i = 0; i < 4; i++) {
            int f4 = (tid + 256 * i) * 4;
            int l = f4 >> 6, n = f4 & 63;
            float4 gv = *(const float4*)&gmp[f4];
            __half2* gp = (__half2*)&GMs[l * SSH + n];
            gp[0] = __floats2half2_rn(gv.x, gv.y);
            gp[1] = __floats2half2_rn(gv.z, gv.w);
            const float* pr = g_proj + (size_t)(rbase + l) * PROJ;
            float lc = lcp[l];
            float4 cv = *(const float4*)(pr + OFF_C + h * NS + n);
            __half2* cp = (__half2*)&Ces[l * SSH + n];
            cp[0] = __floats2half2_rn(cv.x * lc, cv.y * lc);
            cp[1] = __floats2half2_rn(cv.z * lc, cv.w * lc);
            float wl = wlp[l];
            float4 bv = *(const float4*)(pr + OFF_B + h * NS + n);
            Bts[(n + 0) * SSH + l] = __float2half_rn(bv.x * wl);
            Bts[(n + 1) * SSH + l] = __float2half_rn(bv.y * wl);
            Bts[(n + 2) * SSH + l] = __float2half_rn(bv.z * wl);
            Bts[(n + 3) * SSH + l] = __float2half_rn(bv.w * wl);
        }
        #pragma unroll
        for (int i = 0; i < 2; i++) {
            int idx = tid + 256 * i;
            int l = idx >> 3, pc = (idx & 7) * 4;
            float4 xv = *(const float4*)&g_x[(size_t)(rbase + l) * DI + h * HD + p0 + pc];
            xTs[(pc + 0) * SSH + l] = __float2half_rn(xv.x);
            xTs[(pc + 1) * SSH + l] = __float2half_rn(xv.y);
            xTs[(pc + 2) * SSH + l] = __float2half_rn(xv.z);
            xTs[(pc + 3) * SSH + l] = __float2half_rn(xv.w);
        }
        float decay = g_decay[bhc];
        __syncthreads();
        // ---- y = GM@x + Ce@hT ----
        float yA[4] = {0.f, 0.f, 0.f, 0.f};
        float yB[4] = {0.f, 0.f, 0.f, 0.f};
        mm_tile_h(yA, yB, GMs, xTs, mt, nt2, r, cc);
        mm_tile_h(yA, yB, Ces, hTs, mt, nt2, r, cc);
        {
            int tok = rbase + mt * 16 + r;
            int col = h * HD + p0 + nt2 * 8 + 2 * cc;
            float* y0 = g_y + (size_t)tok * DI + col;
            float* y1 = g_y + (size_t)(tok + 8) * DI + col;
            y0[0] = yA[0]; y0[1] = yA[1];
            y0[8] = yB[0]; y0[9] = yB[1];
            y1[0] = yA[2]; y1[1] = yA[3];
            y1[8] = yB[2]; y1[9] = yB[3];
        }
        // ---- h = decay*h + Btw@x ----
        #pragma unroll
        for (int q = 0; q < 4; q++) { hA[q] *= decay; hB[q] *= decay; }
        mm_tile_h(hA, hB, Bts, xTs, mt, nt2, r, cc);
        __syncthreads();
        {
            int pp0 = nt2 * 8 + 2 * cc;
            int nn = mt * 16 + r;
            hTs[(pp0 + 0) * SSH + nn]     = __float2half_rn(hA[0]);
            hTs[(pp0 + 1) * SSH + nn]     = __float2half_rn(hA[1]);
            hTs[(pp0 + 0) * SSH + nn + 8] = __float2half_rn(hA[2]);
            hTs[(pp0 + 1) * SSH + nn + 8] = __float2half_rn(hA[3]);
            hTs[(pp0 + 8) * SSH + nn]     = __float2half_rn(hB[0]);
            hTs[(pp0 + 9) * SSH + nn]     = __float2half_rn(hB[1]);
            hTs[(pp0 + 8) * SSH + nn + 8] = __float2half_rn(hB[2]);
            hTs[(pp0 + 9) * SSH + nn + 8] = __float2half_rn(hB[3]);
        }
    }
}

// ------------------------- K5: gate + RMSNorm (fp16 output) -------------------------
__global__ __launch_bounds__(256) void k_gate(const float* __restrict__ Dp,
                                              const float* __restrict__ wno) {
    int row = blockIdx.x, tid = threadIdx.x;
    __shared__ float red[8];
    const float* yr = g_y + (size_t)row * DI;
    const float* xr = g_x + (size_t)row * DI;
    const float* zr = g_proj + (size_t)row * PROJ + OFF_Z;
    float vals[8];
    float ss = 0.f;
    #pragma unroll
    for (int k = 0; k < 8; k++) {
        int cidx = tid + 256 * k;
        int hh = cidx >> 8;
        float y = yr[cidx] + xr[cidx] * Dp[hh];
        float z = zr[cidx];
        float v = y * silu_f(z);
        vals[k] = v; ss += v * v;
    }
    ss = blk_reduce_sum(ss, red);
    float sc = rsqrtf(ss * (1.0f / DI) + EPSV);
    __half* outp = g_yn + (size_t)row * DI;
    #pragma unroll
    for (int k = 0; k < 8; k++) {
        int cidx = tid + 256 * k;
        outp[cidx] = __float2half_rn(vals[k] * sc * wno[cidx]);
    }
}

// ------------------------- launch -------------------------
extern "C" void kernel_launch(void* const* d_in, const int* in_sizes, int n_in,
                              void* d_out, int out_size) {
    const float* hidden = (const float*)d_in[0];
    const float* w_norm_in = (const float*)d_in[1];
    const float* w_in_proj = (const float*)d_in[2];
    const float* conv_w = (const float*)d_in[3];
    const float* conv_b = (const float*)d_in[4];
    const float* w_dt = (const float*)d_in[5];
    const float* b_dt = (const float*)d_in[6];
    const float* A_log = (const float*)d_in[7];
    const float* Dp = (const float*)d_in[8];
    const float* w_norm_out = (const float*)d_in[9];
    const float* w_out_proj = (const float*)d_in[10];
    float* out = (float*)d_out;

    float *p_proj;
    __half *p_normed, *p_yn, *p_w1tt, *p_w2tt;
    cudaGetSymbolAddress((void**)&p_normed, g_normed);
    cudaGetSymbolAddress((void**)&p_proj, g_proj);
    cudaGetSymbolAddress((void**)&p_yn, g_yn);
    cudaGetSymbolAddress((void**)&p_w1tt, g_w1tt);
    cudaGetSymbolAddress((void**)&p_w2tt, g_w2tt);

    cudaFuncSetAttribute(k_scan, cudaFuncAttributeMaxDynamicSharedMemorySize, SC_SMEM);
    cudaFuncSetAttribute(gemm_hc, cudaFuncAttributeMaxDynamicSharedMemorySize, GSMEM);

    k_tr<<<dim3(DM / 32, PROJP / 32), 256>>>(w_in_proj, p_w1tt, DM, PROJ);
    k_tr<<<dim3(DI / 32, DM / 32), 256>>>(w_out_proj, p_w2tt, DI, DM);
    k_rms_in<<<ROWS, 256>>>(hidden, w_norm_in);
    gemm_hc<<<dim3(PROJP / 128, ROWS / 128), 128, GSMEM>>>(
        p_normed, p_w1tt, nullptr, p_proj, ROWS, PROJ, DM, 0);
    k_conv<<<dim3(DI / 256, ROWS / 8), 256>>>(conv_w, conv_b);
    k_dt<<<ROWS / 16, 256>>>(w_dt, b_dt);
    k_chunkprep<<<dim3(NC, NH, 2), 256>>>(A_log);
    k_scan<<<dim3(8, NH, 2), 256, SC_SMEM>>>();
    k_gate<<<ROWS, 256>>>(Dp, w_norm_out);
    gemm_hc<<<dim3(DM / 128, ROWS / 128), 128, GSMEM>>>(
        p_yn, p_w2tt, hidden, out, ROWS, DM, DI, 1);
}

// round 10
// speedup vs baseline: 5.2181x; 1.1633x over previous
#include <cuda_runtime.h>
#include <cuda_fp16.h>
#include <cstdint>
#include <math.h>

#define ROWS   8192
#define SEQ    4096
#define DM     1024
#define DI     2048
#define NH     8
#define HD     256
#define NS     64
#define CHK    64
#define NC     64
#define PROJ   5128
#define PROJP  5376
#define OFF_Z  0
#define OFF_X  2048
#define OFF_B  4096
#define OFF_C  4608
#define OFF_DT 5120
#define EPSV   1.1920929e-7f

// ------------------------- scratch (device globals) -------------------------
__device__ __half g_normed[ROWS * DM];
__device__ float g_proj[(size_t)ROWS * PROJ];
__device__ float g_x[ROWS * DI];
__device__ __half g_GMh[(size_t)1024 * 4096];      // masked Gram, fp16
__device__ __half g_Ceh[(size_t)1024 * 4096];      // C * exp(lcs), fp16
__device__ __half g_Bth[(size_t)1024 * 4096];      // (B * wl)^T, fp16 [n][l]
__device__ __half g_xTh[(size_t)1024 * 8 * 2048];  // x^T per (bhc, ptile) [p][l]
__device__ float g_decay[1024];
__device__ float g_y[ROWS * DI];
__device__ __half g_yn[ROWS * DI];
__device__ __half g_w1tt[(size_t)PROJP * DM];
__device__ __half g_w2tt[(size_t)DM * DI];

// ------------------------- helpers -------------------------
__device__ __forceinline__ float blk_reduce_sum(float v, float* red) {
    int tid = threadIdx.x;
    #pragma unroll
    for (int o = 16; o > 0; o >>= 1) v += __shfl_xor_sync(0xffffffffu, v, o);
    if ((tid & 31) == 0) red[tid >> 5] = v;
    __syncthreads();
    if (tid < 8) {
        float t = red[tid];
        #pragma unroll
        for (int o = 4; o > 0; o >>= 1) t += __shfl_xor_sync(0xffu, t, o);
        if (tid == 0) red[0] = t;
    }
    __syncthreads();
    return red[0];
}

__device__ __forceinline__ float silu_f(float x) {
    return x / (1.f + __expf(-x));
}

__device__ __forceinline__ uint32_t s2u(const void* p) {
    uint32_t a;
    asm("{ .reg .u64 t; cvta.to.shared.u64 t, %1; cvt.u32.u64 %0, t; }"
        : "=r"(a) : "l"(p));
    return a;
}

__device__ __forceinline__ void cp16s(uint32_t d, const void* s) {
    asm volatile("cp.async.cg.shared.global [%0], [%1], 16;\n" :: "r"(d), "l"(s));
}
__device__ __forceinline__ void cp_commit() {
    asm volatile("cp.async.commit_group;\n" ::);
}
template <int N>
__device__ __forceinline__ void cp_wait() {
    asm volatile("cp.async.wait_group %0;\n" :: "n"(N));
}

__device__ __forceinline__ void mma16h(float* c, const uint32_t* a, const uint32_t* b) {
    asm volatile(
        "mma.sync.aligned.m16n8k16.row.col.f32.f16.f16.f32 "
        "{%0,%1,%2,%3},{%4,%5,%6,%7},{%8,%9},{%0,%1,%2,%3};\n"
        : "+f"(c[0]), "+f"(c[1]), "+f"(c[2]), "+f"(c[3])
        : "r"(a[0]), "r"(a[1]), "r"(a[2]), "r"(a[3]), "r"(b[0]), "r"(b[1]));
}

// ------------------------- K0: transpose + fp16 round weights -------------------------
__global__ __launch_bounds__(256) void k_tr(const float* __restrict__ in,
                                            __half* __restrict__ out,
                                            int Kd, int Nin) {
    __shared__ float t[32][33];
    int k0 = blockIdx.x * 32, n0 = blockIdx.y * 32;
    int tx = threadIdx.x & 31, ty = threadIdx.x >> 5;
    #pragma unroll
    for (int i = ty; i < 32; i += 8) {
        int n = n0 + tx;
        t[i][tx] = (n < Nin) ? in[(size_t)(k0 + i) * Nin + n] : 0.f;
    }
    __syncthreads();
    #pragma unroll
    for (int i = ty; i < 32; i += 8)
        out[(size_t)(n0 + i) * Kd + k0 + tx] = __float2half_rn(t[tx][i]);
}

// ------------------------- K1: input RMSNorm (fp16 output) -------------------------
__global__ __launch_bounds__(256) void k_rms_in(const float* __restrict__ hidden,
                                                const float* __restrict__ w) {
    int row = blockIdx.x, tid = threadIdx.x;
    __shared__ float red[8];
    float4 v = ((const float4*)(hidden + (size_t)row * DM))[tid];
    float ss = v.x * v.x + v.y * v.y + v.z * v.z + v.w * v.w;
    ss = blk_reduce_sum(ss, red);
    float sc = rsqrtf(ss * (1.0f / DM) + EPSV);
    float4 wv = ((const float4*)w)[tid];
    __half2 h0 = __floats2half2_rn(v.x * sc * wv.x, v.y * sc * wv.y);
    __half2 h1 = __floats2half2_rn(v.z * sc * wv.z, v.w * sc * wv.w);
    uint2 pk;
    pk.x = *(uint32_t*)&h0;
    pk.y = *(uint32_t*)&h1;
    ((uint2*)(g_normed + (size_t)row * DM))[tid] = pk;
}

// ------------------------- FP16 mma GEMM: BM=BN=128, 128 thr, 3 stages -------------------------
#define HSTR 48
#define A_HALFS (128 * HSTR)
#define B_HALFS (128 * HSTR)
#define STG_HALFS (A_HALFS + B_HALFS)
#define NSTG 3
#define GSMEM (NSTG * STG_HALFS * 2)

__device__ __forceinline__ void fill_stage(const __half* __restrict__ A,
                                           const __half* __restrict__ BT,
                                           __half* __restrict__ sm, int s,
                                           int bm, int bn, int kt, int K, int tid) {
    __half* As = sm + s * STG_HALFS;
    __half* Bs = As + A_HALFS;
    uint32_t ab = s2u(As), bb = s2u(Bs);
    const __half* Ap = A + (size_t)bm * K + kt * 32;
    #pragma unroll
    for (int j = 0; j < 4; j++) {
        int i = tid + 128 * j;
        int row = i >> 2, c = i & 3;
        cp16s(ab + (row * HSTR + c * 8) * 2, Ap + (size_t)row * K + c * 8);
    }
    const __half* Bp = BT + (size_t)bn * K + kt * 32;
    #pragma unroll
    for (int j = 0; j < 4; j++) {
        int i = tid + 128 * j;
        int row = i >> 2, c = i & 3;
        cp16s(bb + (row * HSTR + c * 8) * 2, Bp + (size_t)row * K + c * 8);
    }
}

__global__ __launch_bounds__(128, 2) void gemm_hc(const __half* __restrict__ A,
                                                  const __half* __restrict__ BT,
                                                  const float* __restrict__ R,
                                                  float* __restrict__ C,
                                                  int M, int N, int K, int addR) {
    extern __shared__ __half smh[];
    int tid = threadIdx.x, lane = tid & 31, warp = tid >> 5;
    int bm = blockIdx.y * 128, bn = blockIdx.x * 128;
    int wm = (warp >> 1) * 64, wn = (warp & 1) * 64;
    int r = lane >> 2, cc = lane & 3;
    float acc[4][8][4];
    #pragma unroll
    for (int mi = 0; mi < 4; mi++)
        #pragma unroll
        for (int ni = 0; ni < 8; ni++)
            #pragma unroll
            for (int q = 0; q < 4; q++) acc[mi][ni][q] = 0.f;

    int nk = K >> 5;
    #pragma unroll
    for (int s = 0; s < NSTG; s++) {
        fill_stage(A, BT, smh, s, bm, bn, s, K, tid);
        cp_commit();
    }

    int s = 0;
    for (int kt = 0; kt < nk; kt++) {
        cp_wait<NSTG - 1>();
        __syncthreads();
        const __half* As = smh + s * STG_HALFS;
        const __half* Bs = As + A_HALFS;
        const __half* arow = As + (wm + r) * HSTR + 4 * cc;
        const __half* brow = Bs + (wn + r) * HSTR + 4 * cc;
        #pragma unroll
        for (int s16 = 0; s16 < 32; s16 += 16) {
            uint32_t af[4][4];
            #pragma unroll
            for (int mi = 0; mi < 4; mi++) {
                uint2 v0 = *(const uint2*)(arow + mi * 16 * HSTR + s16);
                uint2 v1 = *(const uint2*)(arow + (mi * 16 + 8) * HSTR + s16);
                af[mi][0] = v0.x; af[mi][1] = v1.x;
                af[mi][2] = v0.y; af[mi][3] = v1.y;
            }
            uint32_t bf[8][2];
            #pragma unroll
            for (int ni = 0; ni < 8; ni++) {
                uint2 w = *(const uint2*)(brow + ni * 8 * HSTR + s16);
                bf[ni][0] = w.x; bf[ni][1] = w.y;
            }
            #pragma unroll
            for (int mi = 0; mi < 4; mi++)
                #pragma unroll
                for (int ni = 0; ni < 8; ni++)
                    mma16h(acc[mi][ni], af[mi], bf[ni]);
        }
        __syncthreads();
        if (kt + NSTG < nk) {
            fill_stage(A, BT, smh, s, bm, bn, kt + NSTG, K, tid);
            cp_commit();
        } else {
            cp_commit();
        }
        s = (s == NSTG - 1) ? 0 : s + 1;
    }

    #pragma unroll
    for (int mi = 0; mi < 4; mi++) {
        int row = bm + wm + mi * 16 + r;
        #pragma unroll
        for (int ni = 0; ni < 8; ni++) {
            int col = bn + wn + ni * 8 + 2 * cc;
            if (col < N) {
                size_t o0 = (size_t)row * N + col;
                size_t o1 = (size_t)(row + 8) * N + col;
                float2 v0 = make_float2(acc[mi][ni][0], acc[mi][ni][1]);
                float2 v1 = make_float2(acc[mi][ni][2], acc[mi][ni][3]);
                if (addR) {
                    float2 r0 = *(const float2*)(R + o0);
                    float2 r1 = *(const float2*)(R + o1);
                    v0.x += r0.x; v0.y += r0.y;
                    v1.x += r1.x; v1.y += r1.y;
                }
                *(float2*)(C + o0) = v0;
                *(float2*)(C + o1) = v1;
            }
        }
    }
}

// ------------------------- K3: causal depthwise conv + SiLU (rolling window) -------------------------
__global__ __launch_bounds__(256) void k_conv(const float* __restrict__ cw,
                                              const float* __restrict__ cb) {
    int c = blockIdx.x * 256 + threadIdx.x;
    int row0 = blockIdx.y * 8;
    int s0 = row0 & (SEQ - 1);
    float w0 = cw[c * 4 + 0], w1 = cw[c * 4 + 1], w2 = cw[c * 4 + 2], w3 = cw[c * 4 + 3];
    const float* xp = g_proj + (size_t)row0 * PROJ + OFF_X + c;
    float x0 = (s0 >= 3) ? xp[-3 * (int)PROJ] : 0.f;
    float x1 = (s0 >= 2) ? xp[-2 * (int)PROJ] : 0.f;
    float x2 = (s0 >= 1) ? xp[-(int)PROJ] : 0.f;
    float bias = cb[c];
    #pragma unroll
    for (int k = 0; k < 8; k++) {
        float x3 = xp[(size_t)k * PROJ];
        float acc = bias + w0 * x0 + w1 * x1 + w2 * x2 + w3 * x3;
        g_x[(size_t)(row0 + k) * DI + c] = silu_f(acc);
        x0 = x1; x1 = x2; x2 = x3;
    }
}

// ------------------------- K3c: pack x^T fp16 per (b,h,c,ptile) -------------------------
__global__ __launch_bounds__(256) void k_xpack() {
    __shared__ float xs[64][33];
    int pt = blockIdx.x, h = blockIdx.y, z = blockIdx.z;
    int b = z >> 6, c = z & 63;
    int bhc = (b * NH + h) * NC + c;
    int rbase = b * SEQ + c * CHK;
    int tid = threadIdx.x;
    int col0 = h * HD + pt * 32;
    #pragma unroll
    for (int i = 0; i < 8; i++) {
        int e = tid + 256 * i;
        int l = e >> 5, p = e & 31;
        xs[l][p] = g_x[(size_t)(rbase + l) * DI + col0 + p];
    }
    __syncthreads();
    __half* outp = g_xTh + ((size_t)bhc * 8 + pt) * 2048;
    int p = tid >> 3, l0 = (tid & 7) * 8;
    __half2 a0 = __floats2half2_rn(xs[l0 + 0][p], xs[l0 + 1][p]);
    __half2 a1 = __floats2half2_rn(xs[l0 + 2][p], xs[l0 + 3][p]);
    __half2 a2 = __floats2half2_rn(xs[l0 + 4][p], xs[l0 + 5][p]);
    __half2 a3 = __floats2half2_rn(xs[l0 + 6][p], xs[l0 + 7][p]);
    uint4 pk;
    pk.x = *(uint32_t*)&a0; pk.y = *(uint32_t*)&a1;
    pk.z = *(uint32_t*)&a2; pk.w = *(uint32_t*)&a3;
    *(uint4*)(outp + p * 64 + l0) = pk;
}

// ------------------------- K4a: chunk prep (dt fused; fp16 outputs) -------------------------
__global__ __launch_bounds__(256) void k_chunkprep(const float* __restrict__ A_log,
                                                   const float* __restrict__ wdt,
                                                   const float* __restrict__ bdt) {
    int c = blockIdx.x, h = blockIdx.y, b = blockIdx.z;
    int bhc = (b * NH + h) * NC + c;
    int rbase = b * SEQ + c * CHK;
    __shared__ float Bc[64 * 68];
    __shared__ float Cc[64 * 68];
    __shared__ float lcs[64];
    __shared__ float sdt[64];
    __shared__ float draw[64][8];
    int tid = threadIdx.x, lane = tid & 31, w = tid >> 5;
    float A = -__expf(A_log[h]);

    // dt_raw (64 rows x 8)
    #pragma unroll
    for (int i = 0; i < 2; i++) {
        int e = tid + 256 * i;
        int l = e >> 3, j = e & 7;
        draw[l][j] = g_proj[(size_t)(rbase + l) * PROJ + OFF_DT + j];
    }
    // B/C tiles
    #pragma unroll
    for (int i = 0; i < 4; i++) {
        int f = (tid + 256 * i) * 4;
        int l = f >> 6, n = f & 63;
        const float* pr = g_proj + (size_t)(rbase + l) * PROJ;
        float4 bv = *(const float4*)(pr + OFF_B + h * NS + n);
        float4 cv = *(const float4*)(pr + OFF_C + h * NS + n);
        Bc[l * 68 + n + 0] = bv.x; Bc[l * 68 + n + 1] = bv.y;
        Bc[l * 68 + n + 2] = bv.z; Bc[l * 68 + n + 3] = bv.w;
        Cc[l * 68 + n + 0] = cv.x; Cc[l * 68 + n + 1] = cv.y;
        Cc[l * 68 + n + 2] = cv.z; Cc[l * 68 + n + 3] = cv.w;
    }
    __syncthreads();

    // dt: warp w handles rows 8w..8w+7; lane covers dims d0+32q
    {
        int d0 = h * HD + lane;
        float wv[8][8], bb[8];
        #pragma unroll
        for (int j = 0; j < 8; j++)
            #pragma unroll
            for (int q = 0; q < 8; q++) wv[j][q] = wdt[j * DI + d0 + 32 * q];
        #pragma unroll
        for (int q = 0; q < 8; q++) bb[q] = bdt[d0 + 32 * q];
        #pragma unroll
        for (int rr = 0; rr < 8; rr++) {
            int l = w * 8 + rr;
            float dj[8];
            #pragma unroll
            for (int j = 0; j < 8; j++) dj[j] = draw[l][j];
            float acc = 0.f;
            #pragma unroll
            for (int q = 0; q < 8; q++) {
                float v = bb[q];
                #pragma unroll
                for (int j = 0; j < 8; j++) v += dj[j] * wv[j][q];
                acc += (v > 15.f) ? v : __logf(1.f + __expf(v));
            }
            #pragma unroll
            for (int o = 16; o > 0; o >>= 1) acc += __shfl_xor_sync(0xffffffffu, acc, o);
            if (lane == 0) sdt[l] = acc * (1.0f / HD) * A;
        }
    }
    __syncthreads();
    if (tid == 0) {
        float run = 0.f;
        for (int l = 0; l < 64; l++) { run += sdt[l]; lcs[l] = run; }
    }
    __syncthreads();
    float lcs63 = lcs[63];

    // masked Gram -> fp16
    {
        int l = tid >> 2, i0 = (tid & 3) * 16;
        __half* gout = g_GMh + (size_t)bhc * 4096;
        float myl = lcs[l];
        for (int q = 0; q < 16; q++) {
            int i = i0 + q;
            float g = 0.f;
            #pragma unroll
            for (int n = 0; n < 64; n++) g += Cc[l * 68 + n] * Bc[i * 68 + n];
            float m = (i <= l) ? __expf(myl - lcs[i]) : 0.f;
            gout[l * 64 + i] = __float2half_rn(m * g);
        }
    }
    // Ce (C*e^lcs) and Bt ((B*wl)^T) -> fp16
    #pragma unroll
    for (int i = 0; i < 4; i++) {
        int f = (tid + 256 * i) * 4;
        int l = f >> 6, n = f & 63;
        float lc = __expf(lcs[l]);
        __half2* cp = (__half2*)(g_Ceh + (size_t)bhc * 4096 + l * 64 + n);
        cp[0] = __floats2half2_rn(Cc[l * 68 + n + 0] * lc, Cc[l * 68 + n + 1] * lc);
        cp[1] = __floats2half2_rn(Cc[l * 68 + n + 2] * lc, Cc[l * 68 + n + 3] * lc);
        float wl = __expf(lcs63 - lcs[l]);
        __half* bt = g_Bth + (size_t)bhc * 4096;
        bt[(n + 0) * 64 + l] = __float2half_rn(Bc[l * 68 + n + 0] * wl);
        bt[(n + 1) * 64 + l] = __float2half_rn(Bc[l * 68 + n + 1] * wl);
        bt[(n + 2) * 64 + l] = __float2half_rn(Bc[l * 68 + n + 2] * wl);
        bt[(n + 3) * 64 + l] = __float2half_rn(Bc[l * 68 + n + 3] * wl);
    }
    if (tid == 0) g_decay[bhc] = __expf(lcs63);
}

// ------------------------- K4b: pipelined fp16 mma chunk scan -------------------------
#define SSH 80
#define SC_BUF (224 * SSH)           // halves per stage buffer
#define SC_SMEM ((2 * SC_BUF + 32 * SSH) * 2)

__device__ __forceinline__ void scan_prefetch(int bhc, int pt, uint32_t sbuf, int tid) {
    const __half* gm = g_GMh + (size_t)bhc * 4096;
    const __half* ce = g_Ceh + (size_t)bhc * 4096;
    const __half* bt = g_Bth + (size_t)bhc * 4096;
    const __half* xt = g_xTh + ((size_t)bhc * 8 + pt) * 2048;
    int rl = tid >> 3, cs = (tid & 7) * 8;
    cp16s(sbuf + ((0 + rl) * SSH + cs) * 2, gm + rl * 64 + cs);
    cp16s(sbuf + ((32 + rl) * SSH + cs) * 2, gm + (32 + rl) * 64 + cs);
    cp16s(sbuf + ((64 + rl) * SSH + cs) * 2, ce + rl * 64 + cs);
    cp16s(sbuf + ((96 + rl) * SSH + cs) * 2, ce + (32 + rl) * 64 + cs);
    cp16s(sbuf + ((128 + rl) * SSH + cs) * 2, bt + rl * 64 + cs);
    cp16s(sbuf + ((160 + rl) * SSH + cs) * 2, bt + (32 + rl) * 64 + cs);
    cp16s(sbuf + ((192 + rl) * SSH + cs) * 2, xt + rl * 64 + cs);
}

__device__ __forceinline__ void mm_tile_h(float* accA, float* accB,
                                          const __half* Asm, const __half* Bsm,
                                          int mt, int nt2, int r, int cc) {
    const __half* ap = Asm + (mt * 16 + r) * SSH + 4 * cc;
    const __half* bp0 = Bsm + (nt2 * 8 + r) * SSH + 4 * cc;
    const __half* bp1 = bp0 + 8 * SSH;
    #pragma unroll
    for (int s16 = 0; s16 < 64; s16 += 16) {
        uint2 a0 = *(const uint2*)(ap + s16);
        uint2 a1 = *(const uint2*)(ap + 8 * SSH + s16);
        uint32_t af[4] = {a0.x, a1.x, a0.y, a1.y};
        uint2 b0 = *(const uint2*)(bp0 + s16);
        uint2 b1 = *(const uint2*)(bp1 + s16);
        uint32_t bf0[2] = {b0.x, b0.y};
        uint32_t bf1[2] = {b1.x, b1.y};
        mma16h(accA, af, bf0);
        mma16h(accB, af, bf1);
    }
}

__global__ __launch_bounds__(256) void k_scan() {
    extern __shared__ __half smH[];
    uint32_t sb = s2u(smH);
    __half* hTs = smH + 2 * SC_BUF;
    int tid = threadIdx.x, lane = tid & 31, w = tid >> 5;
    int pt = blockIdx.x, h = blockIdx.y, b = blockIdx.z;
    int p0 = pt * 32, bh = b * NH + h;
    int r = lane >> 2, cc = lane & 3;
    int mt = w & 3, nt2 = (w >> 2) * 2;

    for (int e = tid; e < 32 * SSH; e += 256) hTs[e] = __float2half_rn(0.f);
    float hA[4] = {0.f, 0.f, 0.f, 0.f};
    float hB[4] = {0.f, 0.f, 0.f, 0.f};

    scan_prefetch(bh * NC, pt, sb, tid);
    cp_commit();

    for (int c = 0; c < NC; c++) {
        int bhc = bh * NC + c;
        int buf = c & 1;
        const __half* Bf = smH + buf * SC_BUF;
        cp_wait<0>();
        __syncthreads();
        if (c + 1 < NC) scan_prefetch(bhc + 1, pt, sb + (buf ^ 1) * SC_BUF * 2, tid);
        cp_commit();

        const __half* GMs = Bf;
        const __half* Ces = Bf + 64 * SSH;
        const __half* Bts = Bf + 128 * SSH;
        const __half* xTs = Bf + 192 * SSH;
        float decay = g_decay[bhc];

        float yA[4] = {0.f, 0.f, 0.f, 0.f};
        float yB[4] = {0.f, 0.f, 0.f, 0.f};
        mm_tile_h(yA, yB, GMs, xTs, mt, nt2, r, cc);
        mm_tile_h(yA, yB, Ces, hTs, mt, nt2, r, cc);
        {
            int tok = b * SEQ + c * CHK + mt * 16 + r;
            int col = h * HD + p0 + nt2 * 8 + 2 * cc;
            float* y0 = g_y + (size_t)tok * DI + col;
            float* y1 = g_y + (size_t)(tok + 8) * DI + col;
            y0[0] = yA[0]; y0[1] = yA[1];
            y0[8] = yB[0]; y0[9] = yB[1];
            y1[0] = yA[2]; y1[1] = yA[3];
            y1[8] = yB[2]; y1[9] = yB[3];
        }
        #pragma unroll
        for (int q = 0; q < 4; q++) { hA[q] *= decay; hB[q] *= decay; }
        mm_tile_h(hA, hB, Bts, xTs, mt, nt2, r, cc);
        __syncthreads();
        {
            int pp0 = nt2 * 8 + 2 * cc;
            int nn = mt * 16 + r;
            hTs[(pp0 + 0) * SSH + nn]     = __float2half_rn(hA[0]);
            hTs[(pp0 + 1) * SSH + nn]     = __float2half_rn(hA[1]);
            hTs[(pp0 + 0) * SSH + nn + 8] = __float2half_rn(hA[2]);
            hTs[(pp0 + 1) * SSH + nn + 8] = __float2half_rn(hA[3]);
            hTs[(pp0 + 8) * SSH + nn]     = __float2half_rn(hB[0]);
            hTs[(pp0 + 9) * SSH + nn]     = __float2half_rn(hB[1]);
            hTs[(pp0 + 8) * SSH + nn + 8] = __float2half_rn(hB[2]);
            hTs[(pp0 + 9) * SSH + nn + 8] = __float2half_rn(hB[3]);
        }
    }
}

// ------------------------- K5: gate + RMSNorm (fp16 output) -------------------------
__global__ __launch_bounds__(256) void k_gate(const float* __restrict__ Dp,
                                              const float* __restrict__ wno) {
    int row = blockIdx.x, tid = threadIdx.x;
    __shared__ float red[8];
    const float* yr = g_y + (size_t)row * DI;
    const float* xr = g_x + (size_t)row * DI;
    const float* zr = g_proj + (size_t)row * PROJ + OFF_Z;
    float vals[8];
    float ss = 0.f;
    #pragma unroll
    for (int k = 0; k < 8; k++) {
        int cidx = tid + 256 * k;
        int hh = cidx >> 8;
        float y = yr[cidx] + xr[cidx] * Dp[hh];
        float z = zr[cidx];
        float v = y * silu_f(z);
        vals[k] = v; ss += v * v;
    }
    ss = blk_reduce_sum(ss, red);
    float sc = rsqrtf(ss * (1.0f / DI) + EPSV);
    __half* outp = g_yn + (size_t)row * DI;
    #pragma unroll
    for (int k = 0; k < 8; k++) {
        int cidx = tid + 256 * k;
        outp[cidx] = __float2half_rn(vals[k] * sc * wno[cidx]);
    }
}

// ------------------------- launch -------------------------
extern "C" void kernel_launch(void* const* d_in, const int* in_sizes, int n_in,
                              void* d_out, int out_size) {
    const float* hidden = (const float*)d_in[0];
    const float* w_norm_in = (const float*)d_in[1];
    const float* w_in_proj = (const float*)d_in[2];
    const float* conv_w = (const float*)d_in[3];
    const float* conv_b = (const float*)d_in[4];
    const float* w_dt = (const float*)d_in[5];
    const float* b_dt = (const float*)d_in[6];
    const float* A_log = (const float*)d_in[7];
    const float* Dp = (const float*)d_in[8];
    const float* w_norm_out = (const float*)d_in[9];
    const float* w_out_proj = (const float*)d_in[10];
    float* out = (float*)d_out;

    float* p_proj;
    __half *p_normed, *p_yn, *p_w1tt, *p_w2tt;
    cudaGetSymbolAddress((void**)&p_normed, g_normed);
    cudaGetSymbolAddress((void**)&p_proj, g_proj);
    cudaGetSymbolAddress((void**)&p_yn, g_yn);
    cudaGetSymbolAddress((void**)&p_w1tt, g_w1tt);
    cudaGetSymbolAddress((void**)&p_w2tt, g_w2tt);

    cudaFuncSetAttribute(k_scan, cudaFuncAttributeMaxDynamicSharedMemorySize, SC_SMEM);
    cudaFuncSetAttribute(gemm_hc, cudaFuncAttributeMaxDynamicSharedMemorySize, GSMEM);

    k_tr<<<dim3(DM / 32, PROJP / 32), 256>>>(w_in_proj, p_w1tt, DM, PROJ);
    k_tr<<<dim3(DI / 32, DM / 32), 256>>>(w_out_proj, p_w2tt, DI, DM);
    k_rms_in<<<ROWS, 256>>>(hidden, w_norm_in);
    gemm_hc<<<dim3(PROJP / 128, ROWS / 128), 128, GSMEM>>>(
        p_normed, p_w1tt, nullptr, p_proj, ROWS, PROJ, DM, 0);
    k_conv<<<dim3(DI / 256, ROWS / 8), 256>>>(conv_w, conv_b);
    k_xpack<<<dim3(8, NH, 2 * NC), 256>>>();
    k_chunkprep<<<dim3(NC, NH, 2), 256>>>(A_log, w_dt, b_dt);
    k_scan<<<dim3(8, NH, 2), 256, SC_SMEM>>>();
    k_gate<<<ROWS, 256>>>(Dp, w_norm_out);
    gemm_hc<<<dim3(DM / 128, ROWS / 128), 128, GSMEM>>>(
        p_yn, p_w2tt, hidden, out, ROWS, DM, DI, 1);
}